// round 7
// baseline (speedup 1.0000x reference)
#include <cuda_runtime.h>
#include <math.h>
#include <stdint.h>

#define T_TOK 4096
#define H_DIM 1024
#define FF_DIM 2048
#define NEXP 8
#define SS 36
#define STAGES 3

// ---------------- device scratch (allocation-guard safe) --------------------
__device__ int   g_counts[NEXP];
__device__ int   g_tok[NEXP][T_TOK];            // packed: tok | slot<<16
__device__ float g_wslot[2 * T_TOK];
__device__ float g_inner[(size_t)NEXP * T_TOK * FF_DIM];   // 256 MB
__device__ float g_comb[(size_t)2 * T_TOK * H_DIM];        // 32 MB
__device__ float g_w1r[(size_t)NEXP * FF_DIM * H_DIM];     // 64 MB (tf32-rounded)
__device__ float g_w3r[(size_t)NEXP * FF_DIM * H_DIM];     // 64 MB
__device__ float g_w2r[(size_t)NEXP * H_DIM * FF_DIM];     // 64 MB
__device__ float g_xr[(size_t)T_TOK * H_DIM];              // 16 MB

// ---------------- helpers ----------------------------------------------------
__device__ __forceinline__ uint32_t tf32u(float x) {
    uint32_t u; asm("cvt.rna.tf32.f32 %0, %1;" : "=r"(u) : "f"(x)); return u;
}
__device__ __forceinline__ uint4 cvt4(float4 v) {
    uint4 u; u.x = tf32u(v.x); u.y = tf32u(v.y); u.z = tf32u(v.z); u.w = tf32u(v.w);
    return u;
}
__device__ __forceinline__ void mma8(float* c, const uint32_t* a, const uint32_t* b) {
    asm volatile(
        "mma.sync.aligned.m16n8k8.row.col.f32.tf32.tf32.f32 "
        "{%0,%1,%2,%3}, {%4,%5,%6,%7}, {%8,%9}, {%0,%1,%2,%3};"
        : "+f"(c[0]), "+f"(c[1]), "+f"(c[2]), "+f"(c[3])
        : "r"(a[0]), "r"(a[1]), "r"(a[2]), "r"(a[3]), "r"(b[0]), "r"(b[1]));
}
#define LDSM4(r0, r1, r2, r3, addr) \
    asm volatile("ldmatrix.sync.aligned.m8n8.x4.shared.b16 {%0,%1,%2,%3}, [%4];" \
                 : "=r"(r0), "=r"(r1), "=r"(r2), "=r"(r3) : "r"(addr))
#define CP16(dst, src) \
    asm volatile("cp.async.cg.shared.global [%0], [%1], 16;" \
                 :: "r"(dst), "l"(src) : "memory")
#define CPCOMMIT() asm volatile("cp.async.commit_group;" ::: "memory")
#define CPWAIT1()  asm volatile("cp.async.wait_group 1;" ::: "memory")
#define CPWAIT0()  asm volatile("cp.async.wait_group 0;" ::: "memory")

// ---------------- prolog: round weights to tf32, zero counts ----------------
__global__ void round_weights_kernel(const float* __restrict__ w1,
                                     const float* __restrict__ w2,
                                     const float* __restrict__ w3) {
    size_t i = (size_t)blockIdx.x * blockDim.x + threadIdx.x;
    const size_t n4 = (size_t)NEXP * FF_DIM * H_DIM / 4;
    if (i < n4) {
        ((uint4*)g_w1r)[i] = cvt4(((const float4*)w1)[i]);
        ((uint4*)g_w3r)[i] = cvt4(((const float4*)w3)[i]);
        ((uint4*)g_w2r)[i] = cvt4(((const float4*)w2)[i]);
    }
    if (blockIdx.x == 0 && threadIdx.x < NEXP) g_counts[threadIdx.x] = 0;
}

// ---------------- router: 1 warp per token; also writes rounded x -----------
__global__ void router_kernel(const float* __restrict__ x,
                              const float* __restrict__ gw,
                              float* __restrict__ logits_out,
                              int write_logits) {
    int warp = (blockIdx.x * blockDim.x + threadIdx.x) >> 5;
    int lane = threadIdx.x & 31;
    if (warp >= T_TOK) return;

    const float* xr = x + (size_t)warp * H_DIM;
    float xv[32];
#pragma unroll
    for (int i = 0; i < 32; i++) xv[i] = xr[lane + 32 * i];
#pragma unroll
    for (int i = 0; i < 32; i++)
        ((uint32_t*)g_xr)[(size_t)warp * H_DIM + lane + 32 * i] = tf32u(xv[i]);

    float lg[NEXP];
#pragma unroll
    for (int e = 0; e < NEXP; e++) {
        const float* g = gw + (size_t)e * H_DIM;
        float s = 0.f;
#pragma unroll
        for (int i = 0; i < 32; i++) s += xv[i] * g[lane + 32 * i];
#pragma unroll
        for (int o = 16; o > 0; o >>= 1) s += __shfl_xor_sync(0xffffffffu, s, o);
        lg[e] = s;
    }

    if (lane == 0) {
        if (write_logits) {
#pragma unroll
            for (int e = 0; e < NEXP; e++)
                logits_out[(size_t)warp * NEXP + e] = lg[e];
        }
        float mx = lg[0];
#pragma unroll
        for (int e = 1; e < NEXP; e++) mx = fmaxf(mx, lg[e]);
        float p[NEXP], sum = 0.f;
#pragma unroll
        for (int e = 0; e < NEXP; e++) { p[e] = expf(lg[e] - mx); sum += p[e]; }
#pragma unroll
        for (int e = 0; e < NEXP; e++) p[e] /= sum;
        int i1 = 0;
#pragma unroll
        for (int e = 1; e < NEXP; e++) if (p[e] > p[i1]) i1 = e;
        int i2 = (i1 == 0) ? 1 : 0;
#pragma unroll
        for (int e = 0; e < NEXP; e++) if (e != i1 && p[e] > p[i2]) i2 = e;
        float s2 = p[i1] + p[i2];
        int pos = atomicAdd(&g_counts[i1], 1);
        g_tok[i1][pos] = warp;                 // slot 0
        pos = atomicAdd(&g_counts[i2], 1);
        g_tok[i2][pos] = warp | 0x10000;       // slot 1
        g_wslot[warp]         = p[i1] / s2;
        g_wslot[T_TOK + warp] = p[i2] / s2;
    }
}

// ---------------- GEMM1: inner = silu(Xg@W1^T)*(Xg@W3^T) --------------------
// block 128M x 64N(dual) x 32K, 8 warps 4Mx2N, warp 32x32 per matrix.
// 3-stage cp.async ring; kk-level register double buffering.
#define G1_SZ   36864u           // (128+64+64)*SS*4
#define G1_B1O  18432u           // 128*SS*4
#define G1_B3O  27648u           // 192*SS*4

__global__ void __launch_bounds__(256, 2)
gemm1_tc(const float* __restrict__ dummy) {
    extern __shared__ __align__(16) char smc[];
    const uint32_t sbase = (uint32_t)__cvta_generic_to_shared(smc);

    const int e = blockIdx.z;
    const int n = g_counts[e];
    const int row0 = blockIdx.y * 128;
    if (row0 >= n) return;
    const int ff0 = blockIdx.x * 64;

    const int tid = threadIdx.x;
    const int wid = tid >> 5, lane = tid & 31;
    const int wm = wid & 3, wn = wid >> 2;
    const int g = lane >> 2, t = lane & 3;

    // A staging: 4 gathered-row pointers (non-linear); B: 2 base pointers.
    const float* apt[4];
#pragma unroll
    for (int i = 0; i < 4; i++) {
        int r = row0 + (tid >> 3) + 32 * i;
        int tok = (r < n) ? (g_tok[e][r] & 0xFFFF) : 0;
        apt[i] = g_xr + (size_t)tok * H_DIM + (tid & 7) * 4;
    }
    const float* b1p0 = g_w1r + ((size_t)e * FF_DIM + ff0 + (tid >> 3)) * H_DIM + (tid & 7) * 4;
    const float* b3p0 = g_w3r + ((size_t)e * FF_DIM + ff0 + (tid >> 3)) * H_DIM + (tid & 7) * 4;
    const uint32_t off0 = (uint32_t)((tid >> 3) * SS + (tid & 7) * 4) * 4u;
    const uint32_t ostep = 32u * SS * 4u;

    auto issue = [&](int s) {
        uint32_t base = sbase + (uint32_t)(s % STAGES) * G1_SZ;
        int k0 = s * 32;
        uint32_t o = off0;
#pragma unroll
        for (int i = 0; i < 4; i++) { CP16(base + o, apt[i] + k0); o += ostep; }
        o = off0;
#pragma unroll
        for (int i = 0; i < 2; i++) {
            CP16(base + G1_B1O + o, b1p0 + (size_t)32 * i * H_DIM + k0);
            CP16(base + G1_B3O + o, b3p0 + (size_t)32 * i * H_DIM + k0);
            o += ostep;
        }
        CPCOMMIT();
    };

    float acc1[2][4][4], acc3[2][4][4];
#pragma unroll
    for (int mb = 0; mb < 2; mb++)
#pragma unroll
        for (int nb = 0; nb < 4; nb++)
#pragma unroll
            for (int j = 0; j < 4; j++) { acc1[mb][nb][j] = 0.f; acc3[mb][nb][j] = 0.f; }

    // ldmatrix per-lane byte offsets (kk=0); +32B per kk step
    const int lr = lane & 7, lq1 = (lane >> 3) & 1, lq2 = (lane >> 4) & 1;
    uint32_t aLb[2];
#pragma unroll
    for (int mb = 0; mb < 2; mb++)
        aLb[mb] = (uint32_t)((wm * 32 + mb * 16 + lr + lq1 * 8) * SS + lq2 * 4) * 4u;
    uint32_t bLb[2];
#pragma unroll
    for (int p = 0; p < 2; p++)
        bLb[p] = (uint32_t)((wn * 32 + (2 * p + lq2) * 8 + lr) * SS + lq1 * 4) * 4u;

    issue(0); issue(1);

    uint32_t a[2][2][4], b1[2][4][2], b3[2][4][2];   // [buf][...]

    const int NIT = H_DIM / 32;
    for (int it = 0; it < NIT; ++it) {
        if (it + 1 < NIT) CPWAIT1(); else CPWAIT0();
        __syncthreads();
        if (it + STAGES - 1 < NIT) issue(it + STAGES - 1);

        const uint32_t sb  = sbase + (uint32_t)(it % STAGES) * G1_SZ;
        const uint32_t b1b = sb + G1_B1O;
        const uint32_t b3b = sb + G1_B3O;

        // preload kk=0 fragments into buf 0
#pragma unroll
        for (int mb = 0; mb < 2; mb++)
            LDSM4(a[0][mb][0], a[0][mb][1], a[0][mb][2], a[0][mb][3], sb + aLb[mb]);
#pragma unroll
        for (int p = 0; p < 2; p++) {
            LDSM4(b1[0][2*p][0], b1[0][2*p][1], b1[0][2*p+1][0], b1[0][2*p+1][1], b1b + bLb[p]);
            LDSM4(b3[0][2*p][0], b3[0][2*p][1], b3[0][2*p+1][0], b3[0][2*p+1][1], b3b + bLb[p]);
        }

#pragma unroll
        for (int kk = 0; kk < 4; kk++) {
            const int cur = kk & 1, nxt = cur ^ 1;
            if (kk < 3) {
                const uint32_t ko = (uint32_t)(kk + 1) * 32u;
#pragma unroll
                for (int mb = 0; mb < 2; mb++)
                    LDSM4(a[nxt][mb][0], a[nxt][mb][1], a[nxt][mb][2], a[nxt][mb][3],
                          sb + aLb[mb] + ko);
#pragma unroll
                for (int p = 0; p < 2; p++) {
                    LDSM4(b1[nxt][2*p][0], b1[nxt][2*p][1], b1[nxt][2*p+1][0], b1[nxt][2*p+1][1],
                          b1b + bLb[p] + ko);
                    LDSM4(b3[nxt][2*p][0], b3[nxt][2*p][1], b3[nxt][2*p+1][0], b3[nxt][2*p+1][1],
                          b3b + bLb[p] + ko);
                }
            }
#pragma unroll
            for (int mb = 0; mb < 2; mb++)
#pragma unroll
                for (int nb = 0; nb < 4; nb++) {
                    mma8(acc1[mb][nb], a[cur][mb], b1[cur][nb]);
                    mma8(acc3[mb][nb], a[cur][mb], b3[cur][nb]);
                }
        }
    }

    // fused SwiGLU epilogue -> g_inner (tf32-rounded for GEMM2's A operand)
#pragma unroll
    for (int mb = 0; mb < 2; mb++) {
        int r0 = row0 + wm * 32 + mb * 16 + g;
        int r1 = r0 + 8;
#pragma unroll
        for (int nb = 0; nb < 4; nb++) {
            int col = ff0 + wn * 32 + nb * 8 + 2 * t;
            if (r0 < n) {
                float a0 = acc1[mb][nb][0], a1 = acc1[mb][nb][1];
                uint2 v;
                v.x = tf32u((a0 / (1.f + expf(-a0))) * acc3[mb][nb][0]);
                v.y = tf32u((a1 / (1.f + expf(-a1))) * acc3[mb][nb][1]);
                *(uint2*)&g_inner[((size_t)e * T_TOK + r0) * FF_DIM + col] = v;
            }
            if (r1 < n) {
                float a2 = acc1[mb][nb][2], a3 = acc1[mb][nb][3];
                uint2 v;
                v.x = tf32u((a2 / (1.f + expf(-a2))) * acc3[mb][nb][2]);
                v.y = tf32u((a3 / (1.f + expf(-a3))) * acc3[mb][nb][3]);
                *(uint2*)&g_inner[((size_t)e * T_TOK + r1) * FF_DIM + col] = v;
            }
        }
    }
}

// ---------------- GEMM2: comb[slot][tok] = inner @ W2^T ---------------------
// block 128 x 128 x 32; 8 warps 4Mx2N, warp 32x64. 3-stage cp.async ring;
// kk-level register double buffering.
#define G2_SZ  36864u            // 2*128*SS*4
#define G2_BO  18432u

__global__ void __launch_bounds__(256, 2)
gemm2_tc(const float* __restrict__ dummy) {
    extern __shared__ __align__(16) char smc[];
    const uint32_t sbase = (uint32_t)__cvta_generic_to_shared(smc);

    const int e = blockIdx.z;
    const int n = g_counts[e];
    const int row0 = blockIdx.y * 128;
    if (row0 >= n) return;
    const int h0 = blockIdx.x * 128;

    const int tid = threadIdx.x;
    const int wid = tid >> 5, lane = tid & 31;
    const int wm = wid & 3, wn = wid >> 2;
    const int g = lane >> 2, t = lane & 3;

    const float* ap0 = g_inner + ((size_t)e * T_TOK + row0 + (tid >> 3)) * FF_DIM + (tid & 7) * 4;
    const float* bp0 = g_w2r + ((size_t)e * H_DIM + h0 + (tid >> 3)) * FF_DIM + (tid & 7) * 4;
    const uint32_t off0 = (uint32_t)((tid >> 3) * SS + (tid & 7) * 4) * 4u;
    const uint32_t ostep = 32u * SS * 4u;
    const size_t pstep = (size_t)32 * FF_DIM;

    auto issue = [&](int s) {
        uint32_t base = sbase + (uint32_t)(s % STAGES) * G2_SZ;
        int k0 = s * 32;
        const float* ap = ap0 + k0;
        const float* bp = bp0 + k0;
        uint32_t o = off0;
#pragma unroll
        for (int i = 0; i < 4; i++) {
            CP16(base + o, ap);
            CP16(base + G2_BO + o, bp);
            ap += pstep; bp += pstep; o += ostep;
        }
        CPCOMMIT();
    };

    float acc[2][8][4];
#pragma unroll
    for (int mb = 0; mb < 2; mb++)
#pragma unroll
        for (int nb = 0; nb < 8; nb++)
#pragma unroll
            for (int j = 0; j < 4; j++) acc[mb][nb][j] = 0.f;

    const int lr = lane & 7, lq1 = (lane >> 3) & 1, lq2 = (lane >> 4) & 1;
    uint32_t aLb[2];
#pragma unroll
    for (int mb = 0; mb < 2; mb++)
        aLb[mb] = (uint32_t)((wm * 32 + mb * 16 + lr + lq1 * 8) * SS + lq2 * 4) * 4u;
    uint32_t bLb[4];
#pragma unroll
    for (int p = 0; p < 4; p++)
        bLb[p] = (uint32_t)((wn * 64 + (2 * p + lq2) * 8 + lr) * SS + lq1 * 4) * 4u;

    issue(0); issue(1);

    uint32_t a[2][2][4], b[2][8][2];   // [buf][...]

    const int NIT = FF_DIM / 32;
    for (int it = 0; it < NIT; ++it) {
        if (it + 1 < NIT) CPWAIT1(); else CPWAIT0();
        __syncthreads();
        if (it + STAGES - 1 < NIT) issue(it + STAGES - 1);

        const uint32_t sb = sbase + (uint32_t)(it % STAGES) * G2_SZ;
        const uint32_t bb = sb + G2_BO;

        // preload kk=0 fragments into buf 0
#pragma unroll
        for (int mb = 0; mb < 2; mb++)
            LDSM4(a[0][mb][0], a[0][mb][1], a[0][mb][2], a[0][mb][3], sb + aLb[mb]);
#pragma unroll
        for (int p = 0; p < 4; p++)
            LDSM4(b[0][2*p][0], b[0][2*p][1], b[0][2*p+1][0], b[0][2*p+1][1], bb + bLb[p]);

#pragma unroll
        for (int kk = 0; kk < 4; kk++) {
            const int cur = kk & 1, nxt = cur ^ 1;
            if (kk < 3) {
                const uint32_t ko = (uint32_t)(kk + 1) * 32u;
#pragma unroll
                for (int mb = 0; mb < 2; mb++)
                    LDSM4(a[nxt][mb][0], a[nxt][mb][1], a[nxt][mb][2], a[nxt][mb][3],
                          sb + aLb[mb] + ko);
#pragma unroll
                for (int p = 0; p < 4; p++)
                    LDSM4(b[nxt][2*p][0], b[nxt][2*p][1], b[nxt][2*p+1][0], b[nxt][2*p+1][1],
                          bb + bLb[p] + ko);
            }
#pragma unroll
            for (int mb = 0; mb < 2; mb++)
#pragma unroll
                for (int nb = 0; nb < 8; nb++)
                    mma8(acc[mb][nb], a[cur][mb], b[cur][nb]);
        }
    }

    // non-atomic scatter into per-slot combine buffers
#pragma unroll
    for (int mb = 0; mb < 2; mb++) {
        int r0 = row0 + wm * 32 + mb * 16 + g;
        int r1 = r0 + 8;
        int pk0 = (r0 < n) ? g_tok[e][r0] : -1;
        int pk1 = (r1 < n) ? g_tok[e][r1] : -1;
        float* d0 = (pk0 >= 0)
            ? &g_comb[((size_t)(pk0 >> 16) * T_TOK + (pk0 & 0xFFFF)) * H_DIM] : 0;
        float* d1 = (pk1 >= 0)
            ? &g_comb[((size_t)(pk1 >> 16) * T_TOK + (pk1 & 0xFFFF)) * H_DIM] : 0;
#pragma unroll
        for (int nb = 0; nb < 8; nb++) {
            int col = h0 + wn * 64 + nb * 8 + 2 * t;
            if (d0) { float2 v; v.x = acc[mb][nb][0]; v.y = acc[mb][nb][1];
                      *(float2*)&d0[col] = v; }
            if (d1) { float2 v; v.x = acc[mb][nb][2]; v.y = acc[mb][nb][3];
                      *(float2*)&d1[col] = v; }
        }
    }
}

// ---------------- combine: out = w0*comb0 + w1*comb1 ------------------------
__global__ void combine_kernel(float* __restrict__ out) {
    int idx = blockIdx.x * blockDim.x + threadIdx.x;
    const int nq = T_TOK * H_DIM / 4;
    if (idx >= nq) return;
    int tk = idx / (H_DIM / 4);
    float w0 = g_wslot[tk], w1 = g_wslot[T_TOK + tk];
    float4 v0 = ((const float4*)g_comb)[idx];
    float4 v1 = ((const float4*)g_comb)[(size_t)(T_TOK * H_DIM / 4) + idx];
    float4 r;
    r.x = w0 * v0.x + w1 * v1.x;
    r.y = w0 * v0.y + w1 * v1.y;
    r.z = w0 * v0.z + w1 * v1.z;
    r.w = w0 * v0.w + w1 * v1.w;
    ((float4*)out)[idx] = r;
}

// ---------------- launch -----------------------------------------------------
extern "C" void kernel_launch(void* const* d_in, const int* in_sizes, int n_in,
                              void* d_out, int out_size) {
    const float* x  = (const float*)d_in[0];  // [2,2048,1024]
    const float* gw = (const float*)d_in[1];  // [8,1024]
    const float* w1 = (const float*)d_in[2];  // [8,2048,1024]
    const float* w2 = (const float*)d_in[3];  // [8,1024,2048]
    const float* w3 = (const float*)d_in[4];  // [8,2048,1024]
    float* out = (float*)d_out;

    const size_t final_elems = (size_t)T_TOK * H_DIM;
    int write_logits = ((size_t)out_size >= final_elems + (size_t)T_TOK * NEXP) ? 1 : 0;
    float* logits = out + final_elems;

    const int dynsm = STAGES * 36864;   // 110592
    cudaFuncSetAttribute(gemm1_tc, cudaFuncAttributeMaxDynamicSharedMemorySize, dynsm);
    cudaFuncSetAttribute(gemm2_tc, cudaFuncAttributeMaxDynamicSharedMemorySize, dynsm);

    const size_t wq = (size_t)NEXP * FF_DIM * H_DIM / 4;
    round_weights_kernel<<<(int)((wq + 255) / 256), 256>>>(w1, w2, w3);
    router_kernel<<<T_TOK / 8, 256>>>(x, gw, logits, write_logits);

    dim3 g1(FF_DIM / 64, T_TOK / 128, NEXP);   // (32, 32, 8)
    gemm1_tc<<<g1, 256, dynsm>>>(x);

    dim3 g2(H_DIM / 128, T_TOK / 128, NEXP);   // (8, 32, 8)
    gemm2_tc<<<g2, 256, dynsm>>>(x);

    combine_kernel<<<(T_TOK * H_DIM / 4 + 255) / 256, 256>>>(out);
}

// round 8
// speedup vs baseline: 1.0002x; 1.0002x over previous
#include <cuda_runtime.h>
#include <math.h>
#include <stdint.h>

#define T_TOK 4096
#define H_DIM 1024
#define FF_DIM 2048
#define NEXP 8
#define SS 36
#define STAGES 3

// ---------------- device scratch (allocation-guard safe) --------------------
__device__ int   g_counts[NEXP];
__device__ int   g_tok[NEXP][T_TOK];            // packed: tok | slot<<16
__device__ float g_wslot[2 * T_TOK];
__device__ float g_inner[(size_t)NEXP * T_TOK * FF_DIM];   // 256 MB
__device__ float g_comb[(size_t)2 * T_TOK * H_DIM];        // 32 MB
__device__ float g_w1r[(size_t)NEXP * FF_DIM * H_DIM];     // 64 MB (tf32-rounded)
__device__ float g_w3r[(size_t)NEXP * FF_DIM * H_DIM];     // 64 MB
__device__ float g_w2r[(size_t)NEXP * H_DIM * FF_DIM];     // 64 MB
__device__ float g_xr[(size_t)T_TOK * H_DIM];              // 16 MB

// ---------------- helpers ----------------------------------------------------
__device__ __forceinline__ uint32_t tf32u(float x) {
    uint32_t u; asm("cvt.rna.tf32.f32 %0, %1;" : "=r"(u) : "f"(x)); return u;
}
__device__ __forceinline__ uint4 cvt4(float4 v) {
    uint4 u; u.x = tf32u(v.x); u.y = tf32u(v.y); u.z = tf32u(v.z); u.w = tf32u(v.w);
    return u;
}
__device__ __forceinline__ void mma8(float* c, const uint32_t* a, const uint32_t* b) {
    asm volatile(
        "mma.sync.aligned.m16n8k8.row.col.f32.tf32.tf32.f32 "
        "{%0,%1,%2,%3}, {%4,%5,%6,%7}, {%8,%9}, {%0,%1,%2,%3};"
        : "+f"(c[0]), "+f"(c[1]), "+f"(c[2]), "+f"(c[3])
        : "r"(a[0]), "r"(a[1]), "r"(a[2]), "r"(a[3]), "r"(b[0]), "r"(b[1]));
}
#define LDSM4(r0, r1, r2, r3, addr) \
    asm volatile("ldmatrix.sync.aligned.m8n8.x4.shared.b16 {%0,%1,%2,%3}, [%4];" \
                 : "=r"(r0), "=r"(r1), "=r"(r2), "=r"(r3) : "r"(addr))
#define CP16(dst, src) \
    asm volatile("cp.async.cg.shared.global [%0], [%1], 16;" \
                 :: "r"(dst), "l"(src) : "memory")
#define CPCOMMIT() asm volatile("cp.async.commit_group;" ::: "memory")
#define CPWAIT1()  asm volatile("cp.async.wait_group 1;" ::: "memory")
#define CPWAIT0()  asm volatile("cp.async.wait_group 0;" ::: "memory")

// ---------------- prolog: round weights to tf32, zero counts ----------------
__global__ void round_weights_kernel(const float* __restrict__ w1,
                                     const float* __restrict__ w2,
                                     const float* __restrict__ w3) {
    size_t i = (size_t)blockIdx.x * blockDim.x + threadIdx.x;
    const size_t n4 = (size_t)NEXP * FF_DIM * H_DIM / 4;
    if (i < n4) {
        ((uint4*)g_w1r)[i] = cvt4(((const float4*)w1)[i]);
        ((uint4*)g_w3r)[i] = cvt4(((const float4*)w3)[i]);
        ((uint4*)g_w2r)[i] = cvt4(((const float4*)w2)[i]);
    }
    if (blockIdx.x == 0 && threadIdx.x < NEXP) g_counts[threadIdx.x] = 0;
}

// ---------------- router: 1 warp per token; also writes rounded x -----------
__global__ void router_kernel(const float* __restrict__ x,
                              const float* __restrict__ gw,
                              float* __restrict__ logits_out,
                              int write_logits) {
    int warp = (blockIdx.x * blockDim.x + threadIdx.x) >> 5;
    int lane = threadIdx.x & 31;
    if (warp >= T_TOK) return;

    const float* xr = x + (size_t)warp * H_DIM;
    float xv[32];
#pragma unroll
    for (int i = 0; i < 32; i++) xv[i] = xr[lane + 32 * i];
#pragma unroll
    for (int i = 0; i < 32; i++)
        ((uint32_t*)g_xr)[(size_t)warp * H_DIM + lane + 32 * i] = tf32u(xv[i]);

    float lg[NEXP];
#pragma unroll
    for (int e = 0; e < NEXP; e++) {
        const float* g = gw + (size_t)e * H_DIM;
        float s = 0.f;
#pragma unroll
        for (int i = 0; i < 32; i++) s += xv[i] * g[lane + 32 * i];
#pragma unroll
        for (int o = 16; o > 0; o >>= 1) s += __shfl_xor_sync(0xffffffffu, s, o);
        lg[e] = s;
    }

    if (lane == 0) {
        if (write_logits) {
#pragma unroll
            for (int e = 0; e < NEXP; e++)
                logits_out[(size_t)warp * NEXP + e] = lg[e];
        }
        float mx = lg[0];
#pragma unroll
        for (int e = 1; e < NEXP; e++) mx = fmaxf(mx, lg[e]);
        float p[NEXP], sum = 0.f;
#pragma unroll
        for (int e = 0; e < NEXP; e++) { p[e] = expf(lg[e] - mx); sum += p[e]; }
#pragma unroll
        for (int e = 0; e < NEXP; e++) p[e] /= sum;
        int i1 = 0;
#pragma unroll
        for (int e = 1; e < NEXP; e++) if (p[e] > p[i1]) i1 = e;
        int i2 = (i1 == 0) ? 1 : 0;
#pragma unroll
        for (int e = 0; e < NEXP; e++) if (e != i1 && p[e] > p[i2]) i2 = e;
        float s2 = p[i1] + p[i2];
        int pos = atomicAdd(&g_counts[i1], 1);
        g_tok[i1][pos] = warp;                 // slot 0
        pos = atomicAdd(&g_counts[i2], 1);
        g_tok[i2][pos] = warp | 0x10000;       // slot 1
        g_wslot[warp]         = p[i1] / s2;
        g_wslot[T_TOK + warp] = p[i2] / s2;
    }
}

// ---------------- GEMM1: inner = silu(Xg@W1^T)*(Xg@W3^T) --------------------
// ROUND-6 STRUCTURE (proven): block 128M x 64N(dual) x 32K, 8 warps 4Mx2N,
// warp 32x32 per matrix, 3-stage cp.async ring, single-buffer frag loads.
#define G1_SZ   36864u           // (128+64+64)*SS*4
#define G1_B1O  18432u           // 128*SS*4
#define G1_B3O  27648u           // 192*SS*4

__global__ void __launch_bounds__(256, 2)
gemm1_tc(const float* __restrict__ dummy) {
    extern __shared__ __align__(16) char smc[];
    const uint32_t sbase = (uint32_t)__cvta_generic_to_shared(smc);

    const int e = blockIdx.z;
    const int n = g_counts[e];
    const int row0 = blockIdx.y * 128;
    if (row0 >= n) return;
    const int ff0 = blockIdx.x * 64;

    const int tid = threadIdx.x;
    const int wid = tid >> 5, lane = tid & 31;
    const int wm = wid & 3, wn = wid >> 2;
    const int g = lane >> 2, t = lane & 3;

    const float* apt[4];
#pragma unroll
    for (int i = 0; i < 4; i++) {
        int r = row0 + (tid >> 3) + 32 * i;
        int tok = (r < n) ? (g_tok[e][r] & 0xFFFF) : 0;
        apt[i] = g_xr + (size_t)tok * H_DIM + (tid & 7) * 4;
    }
    const float* b1p0 = g_w1r + ((size_t)e * FF_DIM + ff0 + (tid >> 3)) * H_DIM + (tid & 7) * 4;
    const float* b3p0 = g_w3r + ((size_t)e * FF_DIM + ff0 + (tid >> 3)) * H_DIM + (tid & 7) * 4;
    const uint32_t off0 = (uint32_t)((tid >> 3) * SS + (tid & 7) * 4) * 4u;
    const uint32_t ostep = 32u * SS * 4u;

    auto issue = [&](int s) {
        uint32_t base = sbase + (uint32_t)(s % STAGES) * G1_SZ;
        int k0 = s * 32;
        uint32_t o = off0;
#pragma unroll
        for (int i = 0; i < 4; i++) { CP16(base + o, apt[i] + k0); o += ostep; }
        o = off0;
#pragma unroll
        for (int i = 0; i < 2; i++) {
            CP16(base + G1_B1O + o, b1p0 + (size_t)32 * i * H_DIM + k0);
            CP16(base + G1_B3O + o, b3p0 + (size_t)32 * i * H_DIM + k0);
            o += ostep;
        }
        CPCOMMIT();
    };

    float acc1[2][4][4], acc3[2][4][4];
#pragma unroll
    for (int mb = 0; mb < 2; mb++)
#pragma unroll
        for (int nb = 0; nb < 4; nb++)
#pragma unroll
            for (int j = 0; j < 4; j++) { acc1[mb][nb][j] = 0.f; acc3[mb][nb][j] = 0.f; }

    const int lr = lane & 7, lq1 = (lane >> 3) & 1, lq2 = (lane >> 4) & 1;
    uint32_t aLb[2];
#pragma unroll
    for (int mb = 0; mb < 2; mb++)
        aLb[mb] = (uint32_t)((wm * 32 + mb * 16 + lr + lq1 * 8) * SS + lq2 * 4) * 4u;
    uint32_t bLb[2];
#pragma unroll
    for (int p = 0; p < 2; p++)
        bLb[p] = (uint32_t)((wn * 32 + (2 * p + lq2) * 8 + lr) * SS + lq1 * 4) * 4u;

    issue(0); issue(1);

    const int NIT = H_DIM / 32;
    for (int it = 0; it < NIT; ++it) {
        if (it + 1 < NIT) CPWAIT1(); else CPWAIT0();
        __syncthreads();
        if (it + STAGES - 1 < NIT) issue(it + STAGES - 1);

        const uint32_t sb  = sbase + (uint32_t)(it % STAGES) * G1_SZ;
        const uint32_t b1b = sb + G1_B1O;
        const uint32_t b3b = sb + G1_B3O;

#pragma unroll
        for (int kk = 0; kk < 4; kk++) {
            const uint32_t ko = (uint32_t)kk * 32u;
            uint32_t a[2][4], b1[4][2], b3[4][2];
#pragma unroll
            for (int mb = 0; mb < 2; mb++)
                LDSM4(a[mb][0], a[mb][1], a[mb][2], a[mb][3], sb + aLb[mb] + ko);
#pragma unroll
            for (int p = 0; p < 2; p++) {
                LDSM4(b1[2*p][0], b1[2*p][1], b1[2*p+1][0], b1[2*p+1][1], b1b + bLb[p] + ko);
                LDSM4(b3[2*p][0], b3[2*p][1], b3[2*p+1][0], b3[2*p+1][1], b3b + bLb[p] + ko);
            }
#pragma unroll
            for (int mb = 0; mb < 2; mb++)
#pragma unroll
                for (int nb = 0; nb < 4; nb++) {
                    mma8(acc1[mb][nb], a[mb], b1[nb]);
                    mma8(acc3[mb][nb], a[mb], b3[nb]);
                }
        }
    }

    // fused SwiGLU epilogue -> g_inner (tf32-rounded for GEMM2's A operand)
#pragma unroll
    for (int mb = 0; mb < 2; mb++) {
        int r0 = row0 + wm * 32 + mb * 16 + g;
        int r1 = r0 + 8;
#pragma unroll
        for (int nb = 0; nb < 4; nb++) {
            int col = ff0 + wn * 32 + nb * 8 + 2 * t;
            if (r0 < n) {
                float a0 = acc1[mb][nb][0], a1 = acc1[mb][nb][1];
                uint2 v;
                v.x = tf32u((a0 / (1.f + expf(-a0))) * acc3[mb][nb][0]);
                v.y = tf32u((a1 / (1.f + expf(-a1))) * acc3[mb][nb][1]);
                *(uint2*)&g_inner[((size_t)e * T_TOK + r0) * FF_DIM + col] = v;
            }
            if (r1 < n) {
                float a2 = acc1[mb][nb][2], a3 = acc1[mb][nb][3];
                uint2 v;
                v.x = tf32u((a2 / (1.f + expf(-a2))) * acc3[mb][nb][2]);
                v.y = tf32u((a3 / (1.f + expf(-a3))) * acc3[mb][nb][3]);
                *(uint2*)&g_inner[((size_t)e * T_TOK + r1) * FF_DIM + col] = v;
            }
        }
    }
}

// ---------------- GEMM2: comb[slot][tok] = inner @ W2^T ---------------------
// OCCUPANCY EXPERIMENT: block 128M x 64N x 32K, 8 warps 4Mx2N, warp 32x32,
// 2-stage ring (27.6KB/stage), 3 CTAs/SM (24 warps).
#define G2_SZ  27648u            // (128+64)*SS*4
#define G2_BO  18432u            // 128*SS*4
#define G2_STG 2

__global__ void __launch_bounds__(256, 3)
gemm2_tc(const float* __restrict__ dummy) {
    extern __shared__ __align__(16) char smc[];
    const uint32_t sbase = (uint32_t)__cvta_generic_to_shared(smc);

    const int e = blockIdx.z;
    const int n = g_counts[e];
    const int row0 = blockIdx.y * 128;
    if (row0 >= n) return;
    const int h0 = blockIdx.x * 64;

    const int tid = threadIdx.x;
    const int wid = tid >> 5, lane = tid & 31;
    const int wm = wid & 3, wn = wid >> 2;
    const int g = lane >> 2, t = lane & 3;

    const float* ap0 = g_inner + ((size_t)e * T_TOK + row0 + (tid >> 3)) * FF_DIM + (tid & 7) * 4;
    const float* bp0 = g_w2r + ((size_t)e * H_DIM + h0 + (tid >> 3)) * FF_DIM + (tid & 7) * 4;
    const uint32_t off0 = (uint32_t)((tid >> 3) * SS + (tid & 7) * 4) * 4u;
    const uint32_t ostep = 32u * SS * 4u;
    const size_t pstep = (size_t)32 * FF_DIM;

    auto issue = [&](int s) {
        uint32_t base = sbase + (uint32_t)(s % G2_STG) * G2_SZ;
        int k0 = s * 32;
        const float* ap = ap0 + k0;
        uint32_t o = off0;
#pragma unroll
        for (int i = 0; i < 4; i++) { CP16(base + o, ap); ap += pstep; o += ostep; }
        const float* bp = bp0 + k0;
        o = off0;
#pragma unroll
        for (int i = 0; i < 2; i++) {
            CP16(base + G2_BO + o, bp); bp += pstep; o += ostep;
        }
        CPCOMMIT();
    };

    float acc[2][4][4];
#pragma unroll
    for (int mb = 0; mb < 2; mb++)
#pragma unroll
        for (int nb = 0; nb < 4; nb++)
#pragma unroll
            for (int j = 0; j < 4; j++) acc[mb][nb][j] = 0.f;

    const int lr = lane & 7, lq1 = (lane >> 3) & 1, lq2 = (lane >> 4) & 1;
    uint32_t aLb[2];
#pragma unroll
    for (int mb = 0; mb < 2; mb++)
        aLb[mb] = (uint32_t)((wm * 32 + mb * 16 + lr + lq1 * 8) * SS + lq2 * 4) * 4u;
    uint32_t bLb[2];
#pragma unroll
    for (int p = 0; p < 2; p++)
        bLb[p] = (uint32_t)((wn * 32 + (2 * p + lq2) * 8 + lr) * SS + lq1 * 4) * 4u;

    issue(0);

    const int NIT = FF_DIM / 32;
    for (int it = 0; it < NIT; ++it) {
        // 2-stage distance-1 pipeline:
        // group `it` was issued after the PREVIOUS barrier (one full compute
        // iteration of cover). Drain it, make it visible, then issue it+1 into
        // the slot everyone provably finished reading before this barrier.
        CPWAIT0();
        __syncthreads();
        if (it + 1 < NIT) issue(it + 1);

        const uint32_t sb = sbase + (uint32_t)(it % G2_STG) * G2_SZ;
        const uint32_t bb = sb + G2_BO;

#pragma unroll
        for (int kk = 0; kk < 4; kk++) {
            const uint32_t ko = (uint32_t)kk * 32u;
            uint32_t a[2][4], b[4][2];
#pragma unroll
            for (int mb = 0; mb < 2; mb++)
                LDSM4(a[mb][0], a[mb][1], a[mb][2], a[mb][3], sb + aLb[mb] + ko);
#pragma unroll
            for (int p = 0; p < 2; p++)
                LDSM4(b[2*p][0], b[2*p][1], b[2*p+1][0], b[2*p+1][1], bb + bLb[p] + ko);
#pragma unroll
            for (int mb = 0; mb < 2; mb++)
#pragma unroll
                for (int nb = 0; nb < 4; nb++)
                    mma8(acc[mb][nb], a[mb], b[nb]);
        }
    }

    // non-atomic scatter into per-slot combine buffers
#pragma unroll
    for (int mb = 0; mb < 2; mb++) {
        int r0 = row0 + wm * 32 + mb * 16 + g;
        int r1 = r0 + 8;
        int pk0 = (r0 < n) ? g_tok[e][r0] : -1;
        int pk1 = (r1 < n) ? g_tok[e][r1] : -1;
        float* d0 = (pk0 >= 0)
            ? &g_comb[((size_t)(pk0 >> 16) * T_TOK + (pk0 & 0xFFFF)) * H_DIM] : 0;
        float* d1 = (pk1 >= 0)
            ? &g_comb[((size_t)(pk1 >> 16) * T_TOK + (pk1 & 0xFFFF)) * H_DIM] : 0;
#pragma unroll
        for (int nb = 0; nb < 4; nb++) {
            int col = h0 + wn * 32 + nb * 8 + 2 * t;
            if (d0) { float2 v; v.x = acc[mb][nb][0]; v.y = acc[mb][nb][1];
                      *(float2*)&d0[col] = v; }
            if (d1) { float2 v; v.x = acc[mb][nb][2]; v.y = acc[mb][nb][3];
                      *(float2*)&d1[col] = v; }
        }
    }
}

// ---------------- combine: out = w0*comb0 + w1*comb1 ------------------------
__global__ void combine_kernel(float* __restrict__ out) {
    int idx = blockIdx.x * blockDim.x + threadIdx.x;
    const int nq = T_TOK * H_DIM / 4;
    if (idx >= nq) return;
    int tk = idx / (H_DIM / 4);
    float w0 = g_wslot[tk], w1 = g_wslot[T_TOK + tk];
    float4 v0 = ((const float4*)g_comb)[idx];
    float4 v1 = ((const float4*)g_comb)[(size_t)(T_TOK * H_DIM / 4) + idx];
    float4 r;
    r.x = w0 * v0.x + w1 * v1.x;
    r.y = w0 * v0.y + w1 * v1.y;
    r.z = w0 * v0.z + w1 * v1.z;
    r.w = w0 * v0.w + w1 * v1.w;
    ((float4*)out)[idx] = r;
}

// ---------------- launch -----------------------------------------------------
extern "C" void kernel_launch(void* const* d_in, const int* in_sizes, int n_in,
                              void* d_out, int out_size) {
    const float* x  = (const float*)d_in[0];  // [2,2048,1024]
    const float* gw = (const float*)d_in[1];  // [8,1024]
    const float* w1 = (const float*)d_in[2];  // [8,2048,1024]
    const float* w2 = (const float*)d_in[3];  // [8,1024,2048]
    const float* w3 = (const float*)d_in[4];  // [8,2048,1024]
    float* out = (float*)d_out;

    const size_t final_elems = (size_t)T_TOK * H_DIM;
    int write_logits = ((size_t)out_size >= final_elems + (size_t)T_TOK * NEXP) ? 1 : 0;
    float* logits = out + final_elems;

    const int dynsm1 = STAGES * 36864;    // 110592
    const int dynsm2 = G2_STG * 27648;    // 55296 -> 3 CTAs/SM
    cudaFuncSetAttribute(gemm1_tc, cudaFuncAttributeMaxDynamicSharedMemorySize, dynsm1);
    cudaFuncSetAttribute(gemm2_tc, cudaFuncAttributeMaxDynamicSharedMemorySize, dynsm2);

    const size_t wq = (size_t)NEXP * FF_DIM * H_DIM / 4;
    round_weights_kernel<<<(int)((wq + 255) / 256), 256>>>(w1, w2, w3);
    router_kernel<<<T_TOK / 8, 256>>>(x, gw, logits, write_logits);

    dim3 g1(FF_DIM / 64, T_TOK / 128, NEXP);   // (32, 32, 8)
    gemm1_tc<<<g1, 256, dynsm1>>>(x);

    dim3 g2(H_DIM / 64, T_TOK / 128, NEXP);    // (16, 32, 8)
    gemm2_tc<<<g2, 256, dynsm2>>>(x);

    combine_kernel<<<(T_TOK * H_DIM / 4 + 255) / 256, 256>>>(out);
}

// round 9
// speedup vs baseline: 1.2146x; 1.2143x over previous
#include <cuda_runtime.h>
#include <cuda_fp16.h>
#include <math.h>
#include <stdint.h>

#define T_TOK 4096
#define H_DIM 1024
#define FF_DIM 2048
#define NEXP 8
#define SSH 72           // padded row stride in halves (144 B)
#define STAGES 3

// ---------------- device scratch (allocation-guard safe) --------------------
__device__ int      g_counts[NEXP];
__device__ int      g_tok[NEXP][T_TOK];          // packed: tok | slot<<16
__device__ float    g_wslot[2 * T_TOK];
__device__ __half   g_innerh[(size_t)NEXP * T_TOK * FF_DIM];  // 128 MB
__device__ float    g_comb[(size_t)2 * T_TOK * H_DIM];        // 32 MB
__device__ __half   g_w1h[(size_t)NEXP * FF_DIM * H_DIM];     // 32 MB
__device__ __half   g_w3h[(size_t)NEXP * FF_DIM * H_DIM];     // 32 MB
__device__ __half   g_w2h[(size_t)NEXP * H_DIM * FF_DIM];     // 32 MB
__device__ __half   g_xh[(size_t)T_TOK * H_DIM];              // 8 MB

// ---------------- helpers ----------------------------------------------------
__device__ __forceinline__ uint32_t h2u(float a, float b) {
    __half2 h = __floats2half2_rn(a, b);
    return *(uint32_t*)&h;
}
__device__ __forceinline__ uint2 cvt4h(float4 v) {
    uint2 u; u.x = h2u(v.x, v.y); u.y = h2u(v.z, v.w); return u;
}
__device__ __forceinline__ void mma16h(float* c, const uint32_t* a, const uint32_t* b) {
    asm volatile(
        "mma.sync.aligned.m16n8k16.row.col.f32.f16.f16.f32 "
        "{%0,%1,%2,%3}, {%4,%5,%6,%7}, {%8,%9}, {%0,%1,%2,%3};"
        : "+f"(c[0]), "+f"(c[1]), "+f"(c[2]), "+f"(c[3])
        : "r"(a[0]), "r"(a[1]), "r"(a[2]), "r"(a[3]), "r"(b[0]), "r"(b[1]));
}
#define LDSM4(r0, r1, r2, r3, addr) \
    asm volatile("ldmatrix.sync.aligned.m8n8.x4.shared.b16 {%0,%1,%2,%3}, [%4];" \
                 : "=r"(r0), "=r"(r1), "=r"(r2), "=r"(r3) : "r"(addr))
#define CP16(dst, src) \
    asm volatile("cp.async.cg.shared.global [%0], [%1], 16;" \
                 :: "r"(dst), "l"(src) : "memory")
#define CPCOMMIT() asm volatile("cp.async.commit_group;" ::: "memory")
#define CPWAIT1()  asm volatile("cp.async.wait_group 1;" ::: "memory")
#define CPWAIT0()  asm volatile("cp.async.wait_group 0;" ::: "memory")

// ---------------- prolog: convert weights to fp16, zero counts --------------
__global__ void round_weights_kernel(const float* __restrict__ w1,
                                     const float* __restrict__ w2,
                                     const float* __restrict__ w3) {
    size_t i = (size_t)blockIdx.x * blockDim.x + threadIdx.x;
    const size_t n4 = (size_t)NEXP * FF_DIM * H_DIM / 4;
    if (i < n4) {
        ((uint2*)g_w1h)[i] = cvt4h(((const float4*)w1)[i]);
        ((uint2*)g_w3h)[i] = cvt4h(((const float4*)w3)[i]);
        ((uint2*)g_w2h)[i] = cvt4h(((const float4*)w2)[i]);
    }
    if (blockIdx.x == 0 && threadIdx.x < NEXP) g_counts[threadIdx.x] = 0;
}

// ---------------- router: 1 warp per token; also writes fp16 x --------------
__global__ void router_kernel(const float* __restrict__ x,
                              const float* __restrict__ gw,
                              float* __restrict__ logits_out,
                              int write_logits) {
    int warp = (blockIdx.x * blockDim.x + threadIdx.x) >> 5;
    int lane = threadIdx.x & 31;
    if (warp >= T_TOK) return;

    const float* xr = x + (size_t)warp * H_DIM;

    // coalesced fp16 copy of this token row
    for (int i = lane; i < H_DIM / 2; i += 32) {
        float2 v = ((const float2*)xr)[i];
        ((uint32_t*)g_xh)[(size_t)warp * (H_DIM / 2) + i] = h2u(v.x, v.y);
    }

    float xv[32];
#pragma unroll
    for (int i = 0; i < 32; i++) xv[i] = xr[lane + 32 * i];

    float lg[NEXP];
#pragma unroll
    for (int e = 0; e < NEXP; e++) {
        const float* g = gw + (size_t)e * H_DIM;
        float s = 0.f;
#pragma unroll
        for (int i = 0; i < 32; i++) s += xv[i] * g[lane + 32 * i];
#pragma unroll
        for (int o = 16; o > 0; o >>= 1) s += __shfl_xor_sync(0xffffffffu, s, o);
        lg[e] = s;
    }

    if (lane == 0) {
        if (write_logits) {
#pragma unroll
            for (int e = 0; e < NEXP; e++)
                logits_out[(size_t)warp * NEXP + e] = lg[e];
        }
        float mx = lg[0];
#pragma unroll
        for (int e = 1; e < NEXP; e++) mx = fmaxf(mx, lg[e]);
        float p[NEXP], sum = 0.f;
#pragma unroll
        for (int e = 0; e < NEXP; e++) { p[e] = expf(lg[e] - mx); sum += p[e]; }
#pragma unroll
        for (int e = 0; e < NEXP; e++) p[e] /= sum;
        int i1 = 0;
#pragma unroll
        for (int e = 1; e < NEXP; e++) if (p[e] > p[i1]) i1 = e;
        int i2 = (i1 == 0) ? 1 : 0;
#pragma unroll
        for (int e = 0; e < NEXP; e++) if (e != i1 && p[e] > p[i2]) i2 = e;
        float s2 = p[i1] + p[i2];
        int pos = atomicAdd(&g_counts[i1], 1);
        g_tok[i1][pos] = warp;                 // slot 0
        pos = atomicAdd(&g_counts[i2], 1);
        g_tok[i2][pos] = warp | 0x10000;       // slot 1
        g_wslot[warp]         = p[i1] / s2;
        g_wslot[T_TOK + warp] = p[i2] / s2;
    }
}

// ---------------- GEMM1: inner = silu(Xg@W1^T)*(Xg@W3^T), fp16 MMA ----------
// block 128M x 64N(dual) x 64K, 8 warps 4Mx2N, warp 32x32 per matrix.
// 3-stage cp.async ring; fp16 rows padded to 72 halves (144 B).
#define G1_SZ   36864u           // (128+64+64)*144
#define G1_B1O  18432u           // 128*144
#define G1_B3O  27648u           // 192*144

__global__ void __launch_bounds__(256, 2)
gemm1_tc(const float* __restrict__ dummy) {
    extern __shared__ __align__(16) char smc[];
    const uint32_t sbase = (uint32_t)__cvta_generic_to_shared(smc);

    const int e = blockIdx.z;
    const int n = g_counts[e];
    const int row0 = blockIdx.y * 128;
    if (row0 >= n) return;
    const int ff0 = blockIdx.x * 64;

    const int tid = threadIdx.x;
    const int wid = tid >> 5, lane = tid & 31;
    const int wm = wid & 3, wn = wid >> 2;
    const int g = lane >> 2, t = lane & 3;

    // staging: rows of 64 halves = 8 chunks of 16B; 8 threads per row
    const __half* apt[4];
#pragma unroll
    for (int i = 0; i < 4; i++) {
        int r = row0 + (tid >> 3) + 32 * i;
        int tok = (r < n) ? (g_tok[e][r] & 0xFFFF) : 0;
        apt[i] = g_xh + (size_t)tok * H_DIM + (tid & 7) * 8;
    }
    const __half* b1p0 = g_w1h + ((size_t)e * FF_DIM + ff0 + (tid >> 3)) * H_DIM + (tid & 7) * 8;
    const __half* b3p0 = g_w3h + ((size_t)e * FF_DIM + ff0 + (tid >> 3)) * H_DIM + (tid & 7) * 8;
    const uint32_t off0 = (uint32_t)((tid >> 3) * SSH + (tid & 7) * 8) * 2u;
    const uint32_t ostep = 32u * SSH * 2u;

    auto issue = [&](int s) {
        uint32_t base = sbase + (uint32_t)(s % STAGES) * G1_SZ;
        int k0 = s * 64;
        uint32_t o = off0;
#pragma unroll
        for (int i = 0; i < 4; i++) { CP16(base + o, apt[i] + k0); o += ostep; }
        o = off0;
#pragma unroll
        for (int i = 0; i < 2; i++) {
            CP16(base + G1_B1O + o, b1p0 + (size_t)32 * i * H_DIM + k0);
            CP16(base + G1_B3O + o, b3p0 + (size_t)32 * i * H_DIM + k0);
            o += ostep;
        }
        CPCOMMIT();
    };

    float acc1[2][4][4], acc3[2][4][4];
#pragma unroll
    for (int mb = 0; mb < 2; mb++)
#pragma unroll
        for (int nb = 0; nb < 4; nb++)
#pragma unroll
            for (int j = 0; j < 4; j++) { acc1[mb][nb][j] = 0.f; acc3[mb][nb][j] = 0.f; }

    // ldmatrix byte offsets (fp16): A x4 rows lane&15, k-block lane>>4
    uint32_t aLb[2];
#pragma unroll
    for (int mb = 0; mb < 2; mb++)
        aLb[mb] = (uint32_t)((wm * 32 + mb * 16 + (lane & 15)) * SSH) * 2u
                + (uint32_t)(lane >> 4) * 16u;
    // B x4 covers 2 n8k16 frags: rows p*16 + (lane>>4)*8 + (lane&7), k-blk (lane>>3)&1
    uint32_t bLb[2];
#pragma unroll
    for (int p = 0; p < 2; p++)
        bLb[p] = (uint32_t)((wn * 32 + p * 16 + ((lane >> 4) << 3) + (lane & 7)) * SSH) * 2u
               + (uint32_t)((lane >> 3) & 1) * 16u;

    issue(0); issue(1);

    const int NIT = H_DIM / 64;     // 16
    for (int it = 0; it < NIT; ++it) {
        if (it + 1 < NIT) CPWAIT1(); else CPWAIT0();
        __syncthreads();
        if (it + STAGES - 1 < NIT) issue(it + STAGES - 1);

        const uint32_t sb  = sbase + (uint32_t)(it % STAGES) * G1_SZ;
        const uint32_t b1b = sb + G1_B1O;
        const uint32_t b3b = sb + G1_B3O;

#pragma unroll
        for (int kk = 0; kk < 4; kk++) {
            const uint32_t ko = (uint32_t)kk * 32u;   // 16 halves per k-step
            uint32_t a[2][4], b1[4][2], b3[4][2];
#pragma unroll
            for (int mb = 0; mb < 2; mb++)
                LDSM4(a[mb][0], a[mb][1], a[mb][2], a[mb][3], sb + aLb[mb] + ko);
#pragma unroll
            for (int p = 0; p < 2; p++) {
                LDSM4(b1[2*p][0], b1[2*p][1], b1[2*p+1][0], b1[2*p+1][1], b1b + bLb[p] + ko);
                LDSM4(b3[2*p][0], b3[2*p][1], b3[2*p+1][0], b3[2*p+1][1], b3b + bLb[p] + ko);
            }
#pragma unroll
            for (int mb = 0; mb < 2; mb++)
#pragma unroll
                for (int nb = 0; nb < 4; nb++) {
                    mma16h(acc1[mb][nb], a[mb], b1[nb]);
                    mma16h(acc3[mb][nb], a[mb], b3[nb]);
                }
        }
    }

    // fused SwiGLU epilogue -> g_innerh (fp16 for GEMM2's A operand)
#pragma unroll
    for (int mb = 0; mb < 2; mb++) {
        int r0 = row0 + wm * 32 + mb * 16 + g;
        int r1 = r0 + 8;
#pragma unroll
        for (int nb = 0; nb < 4; nb++) {
            int col = ff0 + wn * 32 + nb * 8 + 2 * t;
            if (r0 < n) {
                float a0 = acc1[mb][nb][0], a1 = acc1[mb][nb][1];
                float v0 = (a0 / (1.f + expf(-a0))) * acc3[mb][nb][0];
                float v1 = (a1 / (1.f + expf(-a1))) * acc3[mb][nb][1];
                *(uint32_t*)&g_innerh[((size_t)e * T_TOK + r0) * FF_DIM + col] = h2u(v0, v1);
            }
            if (r1 < n) {
                float a2 = acc1[mb][nb][2], a3 = acc1[mb][nb][3];
                float v2 = (a2 / (1.f + expf(-a2))) * acc3[mb][nb][2];
                float v3 = (a3 / (1.f + expf(-a3))) * acc3[mb][nb][3];
                *(uint32_t*)&g_innerh[((size_t)e * T_TOK + r1) * FF_DIM + col] = h2u(v2, v3);
            }
        }
    }
}

// ---------------- GEMM2: comb[slot][tok] = inner @ W2^T, fp16 MMA -----------
// block 128 x 128 x 64; 8 warps 4Mx2N, warp 32x64. 3-stage cp.async ring.
#define G2_SZ  36864u            // 2*128*144
#define G2_BO  18432u

__global__ void __launch_bounds__(256, 2)
gemm2_tc(const float* __restrict__ dummy) {
    extern __shared__ __align__(16) char smc[];
    const uint32_t sbase = (uint32_t)__cvta_generic_to_shared(smc);

    const int e = blockIdx.z;
    const int n = g_counts[e];
    const int row0 = blockIdx.y * 128;
    if (row0 >= n) return;
    const int h0 = blockIdx.x * 128;

    const int tid = threadIdx.x;
    const int wid = tid >> 5, lane = tid & 31;
    const int wm = wid & 3, wn = wid >> 2;
    const int g = lane >> 2, t = lane & 3;

    const __half* ap0 = g_innerh + ((size_t)e * T_TOK + row0 + (tid >> 3)) * FF_DIM + (tid & 7) * 8;
    const __half* bp0 = g_w2h + ((size_t)e * H_DIM + h0 + (tid >> 3)) * FF_DIM + (tid & 7) * 8;
    const uint32_t off0 = (uint32_t)((tid >> 3) * SSH + (tid & 7) * 8) * 2u;
    const uint32_t ostep = 32u * SSH * 2u;
    const size_t pstep = (size_t)32 * FF_DIM;

    auto issue = [&](int s) {
        uint32_t base = sbase + (uint32_t)(s % STAGES) * G2_SZ;
        int k0 = s * 64;
        const __half* ap = ap0 + k0;
        const __half* bp = bp0 + k0;
        uint32_t o = off0;
#pragma unroll
        for (int i = 0; i < 4; i++) {
            CP16(base + o, ap);
            CP16(base + G2_BO + o, bp);
            ap += pstep; bp += pstep; o += ostep;
        }
        CPCOMMIT();
    };

    float acc[2][8][4];
#pragma unroll
    for (int mb = 0; mb < 2; mb++)
#pragma unroll
        for (int nb = 0; nb < 8; nb++)
#pragma unroll
            for (int j = 0; j < 4; j++) acc[mb][nb][j] = 0.f;

    uint32_t aLb[2];
#pragma unroll
    for (int mb = 0; mb < 2; mb++)
        aLb[mb] = (uint32_t)((wm * 32 + mb * 16 + (lane & 15)) * SSH) * 2u
                + (uint32_t)(lane >> 4) * 16u;
    uint32_t bLb[4];
#pragma unroll
    for (int p = 0; p < 4; p++)
        bLb[p] = (uint32_t)((wn * 64 + p * 16 + ((lane >> 4) << 3) + (lane & 7)) * SSH) * 2u
               + (uint32_t)((lane >> 3) & 1) * 16u;

    issue(0); issue(1);

    const int NIT = FF_DIM / 64;    // 32
    for (int it = 0; it < NIT; ++it) {
        if (it + 1 < NIT) CPWAIT1(); else CPWAIT0();
        __syncthreads();
        if (it + STAGES - 1 < NIT) issue(it + STAGES - 1);

        const uint32_t sb = sbase + (uint32_t)(it % STAGES) * G2_SZ;
        const uint32_t bb = sb + G2_BO;

#pragma unroll
        for (int kk = 0; kk < 4; kk++) {
            const uint32_t ko = (uint32_t)kk * 32u;
            uint32_t a[2][4], b[8][2];
#pragma unroll
            for (int mb = 0; mb < 2; mb++)
                LDSM4(a[mb][0], a[mb][1], a[mb][2], a[mb][3], sb + aLb[mb] + ko);
#pragma unroll
            for (int p = 0; p < 4; p++)
                LDSM4(b[2*p][0], b[2*p][1], b[2*p+1][0], b[2*p+1][1], bb + bLb[p] + ko);
#pragma unroll
            for (int mb = 0; mb < 2; mb++)
#pragma unroll
                for (int nb = 0; nb < 8; nb++)
                    mma16h(acc[mb][nb], a[mb], b[nb]);
        }
    }

    // non-atomic scatter into per-slot combine buffers
#pragma unroll
    for (int mb = 0; mb < 2; mb++) {
        int r0 = row0 + wm * 32 + mb * 16 + g;
        int r1 = r0 + 8;
        int pk0 = (r0 < n) ? g_tok[e][r0] : -1;
        int pk1 = (r1 < n) ? g_tok[e][r1] : -1;
        float* d0 = (pk0 >= 0)
            ? &g_comb[((size_t)(pk0 >> 16) * T_TOK + (pk0 & 0xFFFF)) * H_DIM] : 0;
        float* d1 = (pk1 >= 0)
            ? &g_comb[((size_t)(pk1 >> 16) * T_TOK + (pk1 & 0xFFFF)) * H_DIM] : 0;
#pragma unroll
        for (int nb = 0; nb < 8; nb++) {
            int col = h0 + wn * 64 + nb * 8 + 2 * t;
            if (d0) { float2 v; v.x = acc[mb][nb][0]; v.y = acc[mb][nb][1];
                      *(float2*)&d0[col] = v; }
            if (d1) { float2 v; v.x = acc[mb][nb][2]; v.y = acc[mb][nb][3];
                      *(float2*)&d1[col] = v; }
        }
    }
}

// ---------------- combine: out = w0*comb0 + w1*comb1 ------------------------
__global__ void combine_kernel(float* __restrict__ out) {
    int idx = blockIdx.x * blockDim.x + threadIdx.x;
    const int nq = T_TOK * H_DIM / 4;
    if (idx >= nq) return;
    int tk = idx / (H_DIM / 4);
    float w0 = g_wslot[tk], w1 = g_wslot[T_TOK + tk];
    float4 v0 = ((const float4*)g_comb)[idx];
    float4 v1 = ((const float4*)g_comb)[(size_t)(T_TOK * H_DIM / 4) + idx];
    float4 r;
    r.x = w0 * v0.x + w1 * v1.x;
    r.y = w0 * v0.y + w1 * v1.y;
    r.z = w0 * v0.z + w1 * v1.z;
    r.w = w0 * v0.w + w1 * v1.w;
    ((float4*)out)[idx] = r;
}

// ---------------- launch -----------------------------------------------------
extern "C" void kernel_launch(void* const* d_in, const int* in_sizes, int n_in,
                              void* d_out, int out_size) {
    const float* x  = (const float*)d_in[0];  // [2,2048,1024]
    const float* gw = (const float*)d_in[1];  // [8,1024]
    const float* w1 = (const float*)d_in[2];  // [8,2048,1024]
    const float* w2 = (const float*)d_in[3];  // [8,1024,2048]
    const float* w3 = (const float*)d_in[4];  // [8,2048,1024]
    float* out = (float*)d_out;

    const size_t final_elems = (size_t)T_TOK * H_DIM;
    int write_logits = ((size_t)out_size >= final_elems + (size_t)T_TOK * NEXP) ? 1 : 0;
    float* logits = out + final_elems;

    const int dynsm = STAGES * 36864;   // 110592
    cudaFuncSetAttribute(gemm1_tc, cudaFuncAttributeMaxDynamicSharedMemorySize, dynsm);
    cudaFuncSetAttribute(gemm2_tc, cudaFuncAttributeMaxDynamicSharedMemorySize, dynsm);

    const size_t wq = (size_t)NEXP * FF_DIM * H_DIM / 4;
    round_weights_kernel<<<(int)((wq + 255) / 256), 256>>>(w1, w2, w3);
    router_kernel<<<T_TOK / 8, 256>>>(x, gw, logits, write_logits);

    dim3 g1(FF_DIM / 64, T_TOK / 128, NEXP);   // (32, 32, 8)
    gemm1_tc<<<g1, 256, dynsm>>>(x);

    dim3 g2(H_DIM / 128, T_TOK / 128, NEXP);   // (8, 32, 8)
    gemm2_tc<<<g2, 256, dynsm>>>(x);

    combine_kernel<<<(T_TOK * H_DIM / 4 + 255) / 256, 256>>>(out);
}

// round 10
// speedup vs baseline: 1.3820x; 1.1378x over previous
#include <cuda_runtime.h>
#include <cuda_fp16.h>
#include <math.h>
#include <stdint.h>

#define T_TOK 4096
#define H_DIM 1024
#define FF_DIM 2048
#define NEXP 8
#define SSH 72           // padded row stride in halves (144 B)
#define STAGES 3

// ---------------- device scratch (allocation-guard safe) --------------------
__device__ int      g_counts[NEXP];
__device__ int      g_tok[NEXP][T_TOK];          // packed: tok | slot<<16
__device__ float    g_wslot[2 * T_TOK];
__device__ __half   g_innerh[(size_t)NEXP * T_TOK * FF_DIM];  // 128 MB
__device__ float    g_comb[(size_t)2 * T_TOK * H_DIM];        // 32 MB
__device__ __half   g_w1h[(size_t)NEXP * FF_DIM * H_DIM];     // 32 MB
__device__ __half   g_w3h[(size_t)NEXP * FF_DIM * H_DIM];     // 32 MB
__device__ __half   g_w2h[(size_t)NEXP * H_DIM * FF_DIM];     // 32 MB
__device__ __half   g_xh[(size_t)T_TOK * H_DIM];              // 8 MB

// ---------------- helpers ----------------------------------------------------
__device__ __forceinline__ uint32_t h2u(float a, float b) {
    __half2 h = __floats2half2_rn(a, b);
    return *(uint32_t*)&h;
}
__device__ __forceinline__ uint2 cvt4h(float4 v) {
    uint2 u; u.x = h2u(v.x, v.y); u.y = h2u(v.z, v.w); return u;
}
__device__ __forceinline__ void mma16h(float* c, const uint32_t* a, const uint32_t* b) {
    asm volatile(
        "mma.sync.aligned.m16n8k16.row.col.f32.f16.f16.f32 "
        "{%0,%1,%2,%3}, {%4,%5,%6,%7}, {%8,%9}, {%0,%1,%2,%3};"
        : "+f"(c[0]), "+f"(c[1]), "+f"(c[2]), "+f"(c[3])
        : "r"(a[0]), "r"(a[1]), "r"(a[2]), "r"(a[3]), "r"(b[0]), "r"(b[1]));
}
#define LDSM4(r0, r1, r2, r3, addr) \
    asm volatile("ldmatrix.sync.aligned.m8n8.x4.shared.b16 {%0,%1,%2,%3}, [%4];" \
                 : "=r"(r0), "=r"(r1), "=r"(r2), "=r"(r3) : "r"(addr))
#define CP16(dst, src) \
    asm volatile("cp.async.cg.shared.global [%0], [%1], 16;" \
                 :: "r"(dst), "l"(src) : "memory")
#define CPCOMMIT() asm volatile("cp.async.commit_group;" ::: "memory")
#define CPWAIT1()  asm volatile("cp.async.wait_group 1;" ::: "memory")
#define CPWAIT0()  asm volatile("cp.async.wait_group 0;" ::: "memory")

// ---------------- prolog: convert weights to fp16, zero counts --------------
__global__ void round_weights_kernel(const float* __restrict__ w1,
                                     const float* __restrict__ w2,
                                     const float* __restrict__ w3) {
    size_t i = (size_t)blockIdx.x * blockDim.x + threadIdx.x;
    const size_t n4 = (size_t)NEXP * FF_DIM * H_DIM / 4;
    if (i < n4) {
        ((uint2*)g_w1h)[i] = cvt4h(((const float4*)w1)[i]);
        ((uint2*)g_w3h)[i] = cvt4h(((const float4*)w3)[i]);
        ((uint2*)g_w2h)[i] = cvt4h(((const float4*)w2)[i]);
    }
    if (blockIdx.x == 0 && threadIdx.x < NEXP) g_counts[threadIdx.x] = 0;
}

// ---------------- router: 1 warp per token; also writes fp16 x --------------
__global__ void router_kernel(const float* __restrict__ x,
                              const float* __restrict__ gw,
                              float* __restrict__ logits_out,
                              int write_logits) {
    int warp = (blockIdx.x * blockDim.x + threadIdx.x) >> 5;
    int lane = threadIdx.x & 31;
    if (warp >= T_TOK) return;

    const float* xr = x + (size_t)warp * H_DIM;

    for (int i = lane; i < H_DIM / 2; i += 32) {
        float2 v = ((const float2*)xr)[i];
        ((uint32_t*)g_xh)[(size_t)warp * (H_DIM / 2) + i] = h2u(v.x, v.y);
    }

    float xv[32];
#pragma unroll
    for (int i = 0; i < 32; i++) xv[i] = xr[lane + 32 * i];

    float lg[NEXP];
#pragma unroll
    for (int e = 0; e < NEXP; e++) {
        const float* g = gw + (size_t)e * H_DIM;
        float s = 0.f;
#pragma unroll
        for (int i = 0; i < 32; i++) s += xv[i] * g[lane + 32 * i];
#pragma unroll
        for (int o = 16; o > 0; o >>= 1) s += __shfl_xor_sync(0xffffffffu, s, o);
        lg[e] = s;
    }

    if (lane == 0) {
        if (write_logits) {
#pragma unroll
            for (int e = 0; e < NEXP; e++)
                logits_out[(size_t)warp * NEXP + e] = lg[e];
        }
        float mx = lg[0];
#pragma unroll
        for (int e = 1; e < NEXP; e++) mx = fmaxf(mx, lg[e]);
        float p[NEXP], sum = 0.f;
#pragma unroll
        for (int e = 0; e < NEXP; e++) { p[e] = expf(lg[e] - mx); sum += p[e]; }
#pragma unroll
        for (int e = 0; e < NEXP; e++) p[e] /= sum;
        int i1 = 0;
#pragma unroll
        for (int e = 1; e < NEXP; e++) if (p[e] > p[i1]) i1 = e;
        int i2 = (i1 == 0) ? 1 : 0;
#pragma unroll
        for (int e = 0; e < NEXP; e++) if (e != i1 && p[e] > p[i2]) i2 = e;
        float s2 = p[i1] + p[i2];
        int pos = atomicAdd(&g_counts[i1], 1);
        g_tok[i1][pos] = warp;                 // slot 0
        pos = atomicAdd(&g_counts[i2], 1);
        g_tok[i2][pos] = warp | 0x10000;       // slot 1
        g_wslot[warp]         = p[i1] / s2;
        g_wslot[T_TOK + warp] = p[i2] / s2;
    }
}

// ---------------- GEMM1: inner = silu(Xg@W1^T)*(Xg@W3^T), fp16 MMA ----------
// block 256M x 32N-dual(64 eff) x 64K; 8 warps = 4M x 2N; warp tile 64x32 per
// matrix (acc1 64 + acc3 64 regs). 1 CTA/SM, 3-stage cp.async ring.
#define G1_SZ   55296u           // (256+64+64)*144
#define G1_B1O  36864u           // 256*144
#define G1_B3O  46080u           // 320*144

__global__ void __launch_bounds__(256, 1)
gemm1_tc(const float* __restrict__ dummy) {
    extern __shared__ __align__(16) char smc[];
    const uint32_t sbase = (uint32_t)__cvta_generic_to_shared(smc);

    const int e = blockIdx.z;
    const int n = g_counts[e];
    const int row0 = blockIdx.y * 256;
    if (row0 >= n) return;
    const int ff0 = blockIdx.x * 64;

    const int tid = threadIdx.x;
    const int wid = tid >> 5, lane = tid & 31;
    const int wm = wid & 3, wn = wid >> 2;        // 4M x 2N
    const int g = lane >> 2, t = lane & 3;

    // A: 256 gathered rows, 8 chunk-iters of 32 rows
    const __half* apt[8];
#pragma unroll
    for (int i = 0; i < 8; i++) {
        int r = row0 + (tid >> 3) + 32 * i;
        int tok = (r < n) ? (g_tok[e][r] & 0xFFFF) : 0;
        apt[i] = g_xh + (size_t)tok * H_DIM + (tid & 7) * 8;
    }
    const __half* b1p0 = g_w1h + ((size_t)e * FF_DIM + ff0 + (tid >> 3)) * H_DIM + (tid & 7) * 8;
    const __half* b3p0 = g_w3h + ((size_t)e * FF_DIM + ff0 + (tid >> 3)) * H_DIM + (tid & 7) * 8;
    const uint32_t off0 = (uint32_t)((tid >> 3) * SSH + (tid & 7) * 8) * 2u;
    const uint32_t ostep = 32u * SSH * 2u;

    auto issue = [&](int s) {
        uint32_t base = sbase + (uint32_t)(s % STAGES) * G1_SZ;
        int k0 = s * 64;
        uint32_t o = off0;
#pragma unroll
        for (int i = 0; i < 8; i++) { CP16(base + o, apt[i] + k0); o += ostep; }
        o = off0;
#pragma unroll
        for (int i = 0; i < 2; i++) {
            CP16(base + G1_B1O + o, b1p0 + (size_t)32 * i * H_DIM + k0);
            CP16(base + G1_B3O + o, b3p0 + (size_t)32 * i * H_DIM + k0);
            o += ostep;
        }
        CPCOMMIT();
    };

    float acc1[4][4][4], acc3[4][4][4];
#pragma unroll
    for (int mb = 0; mb < 4; mb++)
#pragma unroll
        for (int nb = 0; nb < 4; nb++)
#pragma unroll
            for (int j = 0; j < 4; j++) { acc1[mb][nb][j] = 0.f; acc3[mb][nb][j] = 0.f; }

    // ldmatrix offsets: A frags mb=0..3 rows wm*64+mb*16
    uint32_t aLb0 = (uint32_t)((wm * 64 + (lane & 15)) * SSH) * 2u
                  + (uint32_t)(lane >> 4) * 16u;
    const uint32_t aMstep = 16u * SSH * 2u;
    // B frag pairs p=0..1 per matrix (nb = 2p, 2p+1), rows wn*32 + ...
    uint32_t bLb[2];
#pragma unroll
    for (int p = 0; p < 2; p++)
        bLb[p] = (uint32_t)((wn * 32 + p * 16 + ((lane >> 4) << 3) + (lane & 7)) * SSH) * 2u
               + (uint32_t)((lane >> 3) & 1) * 16u;

    issue(0); issue(1);

    const int NIT = H_DIM / 64;     // 16
    for (int it = 0; it < NIT; ++it) {
        if (it + 1 < NIT) CPWAIT1(); else CPWAIT0();
        __syncthreads();
        if (it + STAGES - 1 < NIT) issue(it + STAGES - 1);

        const uint32_t sb  = sbase + (uint32_t)(it % STAGES) * G1_SZ;
        const uint32_t b1b = sb + G1_B1O;
        const uint32_t b3b = sb + G1_B3O;

#pragma unroll
        for (int kk = 0; kk < 4; kk++) {
            const uint32_t ko = (uint32_t)kk * 32u;
            uint32_t a[4][4], b1[4][2], b3[4][2];
#pragma unroll
            for (int mb = 0; mb < 4; mb++)
                LDSM4(a[mb][0], a[mb][1], a[mb][2], a[mb][3],
                      sb + aLb0 + (uint32_t)mb * aMstep + ko);
#pragma unroll
            for (int p = 0; p < 2; p++) {
                LDSM4(b1[2*p][0], b1[2*p][1], b1[2*p+1][0], b1[2*p+1][1], b1b + bLb[p] + ko);
                LDSM4(b3[2*p][0], b3[2*p][1], b3[2*p+1][0], b3[2*p+1][1], b3b + bLb[p] + ko);
            }
#pragma unroll
            for (int mb = 0; mb < 4; mb++)
#pragma unroll
                for (int nb = 0; nb < 4; nb++) {
                    mma16h(acc1[mb][nb], a[mb], b1[nb]);
                    mma16h(acc3[mb][nb], a[mb], b3[nb]);
                }
        }
    }

    // fused SwiGLU epilogue -> g_innerh
#pragma unroll
    for (int mb = 0; mb < 4; mb++) {
        int r0 = row0 + wm * 64 + mb * 16 + g;
        int r1 = r0 + 8;
#pragma unroll
        for (int nb = 0; nb < 4; nb++) {
            int col = ff0 + wn * 32 + nb * 8 + 2 * t;
            if (r0 < n) {
                float a0 = acc1[mb][nb][0], a1 = acc1[mb][nb][1];
                float v0 = (a0 / (1.f + expf(-a0))) * acc3[mb][nb][0];
                float v1 = (a1 / (1.f + expf(-a1))) * acc3[mb][nb][1];
                *(uint32_t*)&g_innerh[((size_t)e * T_TOK + r0) * FF_DIM + col] = h2u(v0, v1);
            }
            if (r1 < n) {
                float a2 = acc1[mb][nb][2], a3 = acc1[mb][nb][3];
                float v2 = (a2 / (1.f + expf(-a2))) * acc3[mb][nb][2];
                float v3 = (a3 / (1.f + expf(-a3))) * acc3[mb][nb][3];
                *(uint32_t*)&g_innerh[((size_t)e * T_TOK + r1) * FF_DIM + col] = h2u(v2, v3);
            }
        }
    }
}

// ---------------- GEMM2: comb[slot][tok] = inner @ W2^T, fp16 MMA -----------
// block 128M x 256N x 64K; 8 warps = 2M x 4N; warp tile 64x64 (acc 128 regs).
// 1 CTA/SM, 3-stage cp.async ring.
#define G2_SZ  55296u            // (128+256)*144
#define G2_BO  18432u            // 128*144

__global__ void __launch_bounds__(256, 1)
gemm2_tc(const float* __restrict__ dummy) {
    extern __shared__ __align__(16) char smc[];
    const uint32_t sbase = (uint32_t)__cvta_generic_to_shared(smc);

    const int e = blockIdx.z;
    const int n = g_counts[e];
    const int row0 = blockIdx.y * 128;
    if (row0 >= n) return;
    const int h0 = blockIdx.x * 256;

    const int tid = threadIdx.x;
    const int wid = tid >> 5, lane = tid & 31;
    const int wm = wid & 1, wn = wid >> 1;        // 2M x 4N
    const int g = lane >> 2, t = lane & 3;

    const __half* ap0 = g_innerh + ((size_t)e * T_TOK + row0 + (tid >> 3)) * FF_DIM + (tid & 7) * 8;
    const __half* bp0 = g_w2h + ((size_t)e * H_DIM + h0 + (tid >> 3)) * FF_DIM + (tid & 7) * 8;
    const uint32_t off0 = (uint32_t)((tid >> 3) * SSH + (tid & 7) * 8) * 2u;
    const uint32_t ostep = 32u * SSH * 2u;
    const size_t pstep = (size_t)32 * FF_DIM;

    auto issue = [&](int s) {
        uint32_t base = sbase + (uint32_t)(s % STAGES) * G2_SZ;
        int k0 = s * 64;
        const __half* ap = ap0 + k0;
        uint32_t o = off0;
#pragma unroll
        for (int i = 0; i < 4; i++) { CP16(base + o, ap); ap += pstep; o += ostep; }
        const __half* bp = bp0 + k0;
        o = off0;
#pragma unroll
        for (int i = 0; i < 8; i++) { CP16(base + G2_BO + o, bp); bp += pstep; o += ostep; }
        CPCOMMIT();
    };

    float acc[4][8][4];
#pragma unroll
    for (int mb = 0; mb < 4; mb++)
#pragma unroll
        for (int nb = 0; nb < 8; nb++)
#pragma unroll
            for (int j = 0; j < 4; j++) acc[mb][nb][j] = 0.f;

    uint32_t aLb0 = (uint32_t)((wm * 64 + (lane & 15)) * SSH) * 2u
                  + (uint32_t)(lane >> 4) * 16u;
    const uint32_t aMstep = 16u * SSH * 2u;
    uint32_t bLb[4];
#pragma unroll
    for (int p = 0; p < 4; p++)
        bLb[p] = (uint32_t)((wn * 64 + p * 16 + ((lane >> 4) << 3) + (lane & 7)) * SSH) * 2u
               + (uint32_t)((lane >> 3) & 1) * 16u;

    issue(0); issue(1);

    const int NIT = FF_DIM / 64;    // 32
    for (int it = 0; it < NIT; ++it) {
        if (it + 1 < NIT) CPWAIT1(); else CPWAIT0();
        __syncthreads();
        if (it + STAGES - 1 < NIT) issue(it + STAGES - 1);

        const uint32_t sb = sbase + (uint32_t)(it % STAGES) * G2_SZ;
        const uint32_t bb = sb + G2_BO;

#pragma unroll
        for (int kk = 0; kk < 4; kk++) {
            const uint32_t ko = (uint32_t)kk * 32u;
            uint32_t a[4][4], b[8][2];
#pragma unroll
            for (int mb = 0; mb < 4; mb++)
                LDSM4(a[mb][0], a[mb][1], a[mb][2], a[mb][3],
                      sb + aLb0 + (uint32_t)(mb & 1) * aMstep
                      + (uint32_t)(mb >> 1) * (2u * aMstep) + ko);
#pragma unroll
            for (int p = 0; p < 4; p++)
                LDSM4(b[2*p][0], b[2*p][1], b[2*p+1][0], b[2*p+1][1], bb + bLb[p] + ko);
#pragma unroll
            for (int mb = 0; mb < 4; mb++)
#pragma unroll
                for (int nb = 0; nb < 8; nb++)
                    mma16h(acc[mb][nb], a[mb], b[nb]);
        }
    }

    // non-atomic scatter into per-slot combine buffers
#pragma unroll
    for (int mb = 0; mb < 4; mb++) {
        int r0 = row0 + wm * 64 + mb * 16 + g;
        int r1 = r0 + 8;
        int pk0 = (r0 < n) ? g_tok[e][r0] : -1;
        int pk1 = (r1 < n) ? g_tok[e][r1] : -1;
        float* d0 = (pk0 >= 0)
            ? &g_comb[((size_t)(pk0 >> 16) * T_TOK + (pk0 & 0xFFFF)) * H_DIM] : 0;
        float* d1 = (pk1 >= 0)
            ? &g_comb[((size_t)(pk1 >> 16) * T_TOK + (pk1 & 0xFFFF)) * H_DIM] : 0;
#pragma unroll
        for (int nb = 0; nb < 8; nb++) {
            int col = h0 + wn * 64 + nb * 8 + 2 * t;
            if (d0) { float2 v; v.x = acc[mb][nb][0]; v.y = acc[mb][nb][1];
                      *(float2*)&d0[col] = v; }
            if (d1) { float2 v; v.x = acc[mb][nb][2]; v.y = acc[mb][nb][3];
                      *(float2*)&d1[col] = v; }
        }
    }
}

// ---------------- combine: out = w0*comb0 + w1*comb1 ------------------------
__global__ void combine_kernel(float* __restrict__ out) {
    int idx = blockIdx.x * blockDim.x + threadIdx.x;
    const int nq = T_TOK * H_DIM / 4;
    if (idx >= nq) return;
    int tk = idx / (H_DIM / 4);
    float w0 = g_wslot[tk], w1 = g_wslot[T_TOK + tk];
    float4 v0 = ((const float4*)g_comb)[idx];
    float4 v1 = ((const float4*)g_comb)[(size_t)(T_TOK * H_DIM / 4) + idx];
    float4 r;
    r.x = w0 * v0.x + w1 * v1.x;
    r.y = w0 * v0.y + w1 * v1.y;
    r.z = w0 * v0.z + w1 * v1.z;
    r.w = w0 * v0.w + w1 * v1.w;
    ((float4*)out)[idx] = r;
}

// ---------------- launch -----------------------------------------------------
extern "C" void kernel_launch(void* const* d_in, const int* in_sizes, int n_in,
                              void* d_out, int out_size) {
    const float* x  = (const float*)d_in[0];  // [2,2048,1024]
    const float* gw = (const float*)d_in[1];  // [8,1024]
    const float* w1 = (const float*)d_in[2];  // [8,2048,1024]
    const float* w2 = (const float*)d_in[3];  // [8,1024,2048]
    const float* w3 = (const float*)d_in[4];  // [8,2048,1024]
    float* out = (float*)d_out;

    const size_t final_elems = (size_t)T_TOK * H_DIM;
    int write_logits = ((size_t)out_size >= final_elems + (size_t)T_TOK * NEXP) ? 1 : 0;
    float* logits = out + final_elems;

    const int dynsm = STAGES * 55296;   // 165888
    cudaFuncSetAttribute(gemm1_tc, cudaFuncAttributeMaxDynamicSharedMemorySize, dynsm);
    cudaFuncSetAttribute(gemm2_tc, cudaFuncAttributeMaxDynamicSharedMemorySize, dynsm);

    const size_t wq = (size_t)NEXP * FF_DIM * H_DIM / 4;
    round_weights_kernel<<<(int)((wq + 255) / 256), 256>>>(w1, w2, w3);
    router_kernel<<<T_TOK / 8, 256>>>(x, gw, logits, write_logits);

    dim3 g1(FF_DIM / 64, T_TOK / 256, NEXP);   // (32, 16, 8)
    gemm1_tc<<<g1, 256, dynsm>>>(x);

    dim3 g2(H_DIM / 256, T_TOK / 128, NEXP);   // (4, 32, 8)
    gemm2_tc<<<g2, 256, dynsm>>>(x);

    combine_kernel<<<(T_TOK * H_DIM / 4 + 255) / 256, 256>>>(out);
}

// round 11
// speedup vs baseline: 1.6781x; 1.2143x over previous
#include <cuda_runtime.h>
#include <cuda_fp16.h>
#include <math.h>
#include <stdint.h>

#define T_TOK 4096
#define H_DIM 1024
#define FF_DIM 2048
#define NEXP 8
#define SSH 72           // padded row stride in halves (144 B)
#define STAGES 3

// ---------------- device scratch (allocation-guard safe) --------------------
__device__ int      g_counts[NEXP];
__device__ int      g_tok[NEXP][T_TOK];          // packed: tok | slot<<16
__device__ float    g_wslot[2 * T_TOK];
__device__ __half   g_innerh[(size_t)NEXP * T_TOK * FF_DIM];  // 128 MB
__device__ float    g_comb[(size_t)2 * T_TOK * H_DIM];        // 32 MB
__device__ __half   g_w1h[(size_t)NEXP * FF_DIM * H_DIM];     // 32 MB
__device__ __half   g_w3h[(size_t)NEXP * FF_DIM * H_DIM];     // 32 MB
__device__ __half   g_w2h[(size_t)NEXP * H_DIM * FF_DIM];     // 32 MB
__device__ __half   g_xh[(size_t)T_TOK * H_DIM];              // 8 MB

// ---------------- helpers ----------------------------------------------------
__device__ __forceinline__ uint32_t h2u(float a, float b) {
    __half2 h = __floats2half2_rn(a, b);
    return *(uint32_t*)&h;
}
__device__ __forceinline__ uint2 cvt4h(float4 v) {
    uint2 u; u.x = h2u(v.x, v.y); u.y = h2u(v.z, v.w); return u;
}
__device__ __forceinline__ void mma16h(float* c, const uint32_t* a, const uint32_t* b) {
    asm volatile(
        "mma.sync.aligned.m16n8k16.row.col.f32.f16.f16.f32 "
        "{%0,%1,%2,%3}, {%4,%5,%6,%7}, {%8,%9}, {%0,%1,%2,%3};"
        : "+f"(c[0]), "+f"(c[1]), "+f"(c[2]), "+f"(c[3])
        : "r"(a[0]), "r"(a[1]), "r"(a[2]), "r"(a[3]), "r"(b[0]), "r"(b[1]));
}
#define LDSM4(r0, r1, r2, r3, addr) \
    asm volatile("ldmatrix.sync.aligned.m8n8.x4.shared.b16 {%0,%1,%2,%3}, [%4];" \
                 : "=r"(r0), "=r"(r1), "=r"(r2), "=r"(r3) : "r"(addr))
#define CP16(dst, src) \
    asm volatile("cp.async.cg.shared.global [%0], [%1], 16;" \
                 :: "r"(dst), "l"(src) : "memory")
#define CPCOMMIT() asm volatile("cp.async.commit_group;" ::: "memory")
#define CPWAIT1()  asm volatile("cp.async.wait_group 1;" ::: "memory")
#define CPWAIT0()  asm volatile("cp.async.wait_group 0;" ::: "memory")

// ---------------- prolog: convert weights to fp16, zero counts --------------
__global__ void round_weights_kernel(const float* __restrict__ w1,
                                     const float* __restrict__ w2,
                                     const float* __restrict__ w3) {
    size_t i = (size_t)blockIdx.x * blockDim.x + threadIdx.x;
    const size_t n4 = (size_t)NEXP * FF_DIM * H_DIM / 4;
    if (i < n4) {
        ((uint2*)g_w1h)[i] = cvt4h(((const float4*)w1)[i]);
        ((uint2*)g_w3h)[i] = cvt4h(((const float4*)w3)[i]);
        ((uint2*)g_w2h)[i] = cvt4h(((const float4*)w2)[i]);
    }
    if (blockIdx.x == 0 && threadIdx.x < NEXP) g_counts[threadIdx.x] = 0;
}

// ---------------- router: 1 warp per token; also writes fp16 x --------------
__global__ void router_kernel(const float* __restrict__ x,
                              const float* __restrict__ gw,
                              float* __restrict__ logits_out,
                              int write_logits) {
    int warp = (blockIdx.x * blockDim.x + threadIdx.x) >> 5;
    int lane = threadIdx.x & 31;
    if (warp >= T_TOK) return;

    const float* xr = x + (size_t)warp * H_DIM;

    for (int i = lane; i < H_DIM / 2; i += 32) {
        float2 v = ((const float2*)xr)[i];
        ((uint32_t*)g_xh)[(size_t)warp * (H_DIM / 2) + i] = h2u(v.x, v.y);
    }

    float xv[32];
#pragma unroll
    for (int i = 0; i < 32; i++) xv[i] = xr[lane + 32 * i];

    float lg[NEXP];
#pragma unroll
    for (int e = 0; e < NEXP; e++) {
        const float* g = gw + (size_t)e * H_DIM;
        float s = 0.f;
#pragma unroll
        for (int i = 0; i < 32; i++) s += xv[i] * g[lane + 32 * i];
#pragma unroll
        for (int o = 16; o > 0; o >>= 1) s += __shfl_xor_sync(0xffffffffu, s, o);
        lg[e] = s;
    }

    if (lane == 0) {
        if (write_logits) {
#pragma unroll
            for (int e = 0; e < NEXP; e++)
                logits_out[(size_t)warp * NEXP + e] = lg[e];
        }
        float mx = lg[0];
#pragma unroll
        for (int e = 1; e < NEXP; e++) mx = fmaxf(mx, lg[e]);
        float p[NEXP], sum = 0.f;
#pragma unroll
        for (int e = 0; e < NEXP; e++) { p[e] = expf(lg[e] - mx); sum += p[e]; }
#pragma unroll
        for (int e = 0; e < NEXP; e++) p[e] /= sum;
        int i1 = 0;
#pragma unroll
        for (int e = 1; e < NEXP; e++) if (p[e] > p[i1]) i1 = e;
        int i2 = (i1 == 0) ? 1 : 0;
#pragma unroll
        for (int e = 0; e < NEXP; e++) if (e != i1 && p[e] > p[i2]) i2 = e;
        float s2 = p[i1] + p[i2];
        int pos = atomicAdd(&g_counts[i1], 1);
        g_tok[i1][pos] = warp;                 // slot 0
        pos = atomicAdd(&g_counts[i2], 1);
        g_tok[i2][pos] = warp | 0x10000;       // slot 1
        g_wslot[warp]         = p[i1] / s2;
        g_wslot[T_TOK + warp] = p[i2] / s2;
    }
}

// ---------------- GEMM1: inner = silu(Xg@W1^T)*(Xg@W3^T), fp16 MMA ----------
// block 128M x 32N-dual(64 eff) x 64K; 4 warps = 2M x 2N; warp tile 64x32 per
// matrix. 128 threads, 2 CTAs/SM, 3-stage cp.async ring.
#define G1_SZ   36864u           // (128+64+64)*144
#define G1_B1O  18432u           // 128*144
#define G1_B3O  27648u           // 192*144

__global__ void __launch_bounds__(128, 2)
gemm1_tc(const float* __restrict__ dummy) {
    extern __shared__ __align__(16) char smc[];
    const uint32_t sbase = (uint32_t)__cvta_generic_to_shared(smc);

    const int e = blockIdx.z;
    const int n = g_counts[e];
    const int row0 = blockIdx.y * 128;
    if (row0 >= n) return;
    const int ff0 = blockIdx.x * 64;

    const int tid = threadIdx.x;
    const int wid = tid >> 5, lane = tid & 31;
    const int wm = wid & 1, wn = wid >> 1;        // 2M x 2N
    const int g = lane >> 2, t = lane & 3;

    // staging: 16 rows per pass (128 thr / 8 chunks-per-row)
    const __half* apt[8];
#pragma unroll
    for (int i = 0; i < 8; i++) {
        int r = row0 + (tid >> 3) + 16 * i;
        int tok = (r < n) ? (g_tok[e][r] & 0xFFFF) : 0;
        apt[i] = g_xh + (size_t)tok * H_DIM + (tid & 7) * 8;
    }
    const __half* b1p0 = g_w1h + ((size_t)e * FF_DIM + ff0 + (tid >> 3)) * H_DIM + (tid & 7) * 8;
    const __half* b3p0 = g_w3h + ((size_t)e * FF_DIM + ff0 + (tid >> 3)) * H_DIM + (tid & 7) * 8;
    const uint32_t off0 = (uint32_t)((tid >> 3) * SSH + (tid & 7) * 8) * 2u;
    const uint32_t ostep = 16u * SSH * 2u;

    auto issue = [&](int s) {
        uint32_t base = sbase + (uint32_t)(s % STAGES) * G1_SZ;
        int k0 = s * 64;
        uint32_t o = off0;
#pragma unroll
        for (int i = 0; i < 8; i++) { CP16(base + o, apt[i] + k0); o += ostep; }
        o = off0;
#pragma unroll
        for (int i = 0; i < 4; i++) {
            CP16(base + G1_B1O + o, b1p0 + (size_t)16 * i * H_DIM + k0);
            CP16(base + G1_B3O + o, b3p0 + (size_t)16 * i * H_DIM + k0);
            o += ostep;
        }
        CPCOMMIT();
    };

    float acc1[4][4][4], acc3[4][4][4];
#pragma unroll
    for (int mb = 0; mb < 4; mb++)
#pragma unroll
        for (int nb = 0; nb < 4; nb++)
#pragma unroll
            for (int j = 0; j < 4; j++) { acc1[mb][nb][j] = 0.f; acc3[mb][nb][j] = 0.f; }

    uint32_t aLb0 = (uint32_t)((wm * 64 + (lane & 15)) * SSH) * 2u
                  + (uint32_t)(lane >> 4) * 16u;
    const uint32_t aMstep = 16u * SSH * 2u;
    uint32_t bLb[2];
#pragma unroll
    for (int p = 0; p < 2; p++)
        bLb[p] = (uint32_t)((wn * 32 + p * 16 + ((lane >> 4) << 3) + (lane & 7)) * SSH) * 2u
               + (uint32_t)((lane >> 3) & 1) * 16u;

    issue(0); issue(1);

    const int NIT = H_DIM / 64;     // 16
    for (int it = 0; it < NIT; ++it) {
        if (it + 1 < NIT) CPWAIT1(); else CPWAIT0();
        __syncthreads();
        if (it + STAGES - 1 < NIT) issue(it + STAGES - 1);

        const uint32_t sb  = sbase + (uint32_t)(it % STAGES) * G1_SZ;
        const uint32_t b1b = sb + G1_B1O;
        const uint32_t b3b = sb + G1_B3O;

#pragma unroll
        for (int kk = 0; kk < 4; kk++) {
            const uint32_t ko = (uint32_t)kk * 32u;
            uint32_t a[4][4], b1[4][2], b3[4][2];
#pragma unroll
            for (int mb = 0; mb < 4; mb++)
                LDSM4(a[mb][0], a[mb][1], a[mb][2], a[mb][3],
                      sb + aLb0 + (uint32_t)mb * aMstep + ko);
#pragma unroll
            for (int p = 0; p < 2; p++) {
                LDSM4(b1[2*p][0], b1[2*p][1], b1[2*p+1][0], b1[2*p+1][1], b1b + bLb[p] + ko);
                LDSM4(b3[2*p][0], b3[2*p][1], b3[2*p+1][0], b3[2*p+1][1], b3b + bLb[p] + ko);
            }
#pragma unroll
            for (int mb = 0; mb < 4; mb++)
#pragma unroll
                for (int nb = 0; nb < 4; nb++) {
                    mma16h(acc1[mb][nb], a[mb], b1[nb]);
                    mma16h(acc3[mb][nb], a[mb], b3[nb]);
                }
        }
    }

    // fused SwiGLU epilogue -> g_innerh
#pragma unroll
    for (int mb = 0; mb < 4; mb++) {
        int r0 = row0 + wm * 64 + mb * 16 + g;
        int r1 = r0 + 8;
#pragma unroll
        for (int nb = 0; nb < 4; nb++) {
            int col = ff0 + wn * 32 + nb * 8 + 2 * t;
            if (r0 < n) {
                float a0 = acc1[mb][nb][0], a1 = acc1[mb][nb][1];
                float v0 = (a0 / (1.f + expf(-a0))) * acc3[mb][nb][0];
                float v1 = (a1 / (1.f + expf(-a1))) * acc3[mb][nb][1];
                *(uint32_t*)&g_innerh[((size_t)e * T_TOK + r0) * FF_DIM + col] = h2u(v0, v1);
            }
            if (r1 < n) {
                float a2 = acc1[mb][nb][2], a3 = acc1[mb][nb][3];
                float v2 = (a2 / (1.f + expf(-a2))) * acc3[mb][nb][2];
                float v3 = (a3 / (1.f + expf(-a3))) * acc3[mb][nb][3];
                *(uint32_t*)&g_innerh[((size_t)e * T_TOK + r1) * FF_DIM + col] = h2u(v2, v3);
            }
        }
    }
}

// ---------------- GEMM2: comb[slot][tok] = inner @ W2^T, fp16 MMA -----------
// block 128M x 128N x 64K; 4 warps = 2M x 2N; warp tile 64x64.
// 128 threads, 2 CTAs/SM, 3-stage cp.async ring.
#define G2_SZ  36864u            // (128+128)*144
#define G2_BO  18432u            // 128*144

__global__ void __launch_bounds__(128, 2)
gemm2_tc(const float* __restrict__ dummy) {
    extern __shared__ __align__(16) char smc[];
    const uint32_t sbase = (uint32_t)__cvta_generic_to_shared(smc);

    const int e = blockIdx.z;
    const int n = g_counts[e];
    const int row0 = blockIdx.y * 128;
    if (row0 >= n) return;
    const int h0 = blockIdx.x * 128;

    const int tid = threadIdx.x;
    const int wid = tid >> 5, lane = tid & 31;
    const int wm = wid & 1, wn = wid >> 1;        // 2M x 2N
    const int g = lane >> 2, t = lane & 3;

    const __half* ap0 = g_innerh + ((size_t)e * T_TOK + row0 + (tid >> 3)) * FF_DIM + (tid & 7) * 8;
    const __half* bp0 = g_w2h + ((size_t)e * H_DIM + h0 + (tid >> 3)) * FF_DIM + (tid & 7) * 8;
    const uint32_t off0 = (uint32_t)((tid >> 3) * SSH + (tid & 7) * 8) * 2u;
    const uint32_t ostep = 16u * SSH * 2u;
    const size_t pstep = (size_t)16 * FF_DIM;

    auto issue = [&](int s) {
        uint32_t base = sbase + (uint32_t)(s % STAGES) * G2_SZ;
        int k0 = s * 64;
        const __half* ap = ap0 + k0;
        const __half* bp = bp0 + k0;
        uint32_t o = off0;
#pragma unroll
        for (int i = 0; i < 8; i++) {
            CP16(base + o, ap);
            CP16(base + G2_BO + o, bp);
            ap += pstep; bp += pstep; o += ostep;
        }
        CPCOMMIT();
    };

    float acc[4][8][4];
#pragma unroll
    for (int mb = 0; mb < 4; mb++)
#pragma unroll
        for (int nb = 0; nb < 8; nb++)
#pragma unroll
            for (int j = 0; j < 4; j++) acc[mb][nb][j] = 0.f;

    uint32_t aLb0 = (uint32_t)((wm * 64 + (lane & 15)) * SSH) * 2u
                  + (uint32_t)(lane >> 4) * 16u;
    const uint32_t aMstep = 16u * SSH * 2u;
    uint32_t bLb[4];
#pragma unroll
    for (int p = 0; p < 4; p++)
        bLb[p] = (uint32_t)((wn * 64 + p * 16 + ((lane >> 4) << 3) + (lane & 7)) * SSH) * 2u
               + (uint32_t)((lane >> 3) & 1) * 16u;

    issue(0); issue(1);

    const int NIT = FF_DIM / 64;    // 32
    for (int it = 0; it < NIT; ++it) {
        if (it + 1 < NIT) CPWAIT1(); else CPWAIT0();
        __syncthreads();
        if (it + STAGES - 1 < NIT) issue(it + STAGES - 1);

        const uint32_t sb = sbase + (uint32_t)(it % STAGES) * G2_SZ;
        const uint32_t bb = sb + G2_BO;

#pragma unroll
        for (int kk = 0; kk < 4; kk++) {
            const uint32_t ko = (uint32_t)kk * 32u;
            uint32_t a[4][4], b[8][2];
#pragma unroll
            for (int mb = 0; mb < 4; mb++)
                LDSM4(a[mb][0], a[mb][1], a[mb][2], a[mb][3],
                      sb + aLb0 + (uint32_t)mb * aMstep + ko);
#pragma unroll
            for (int p = 0; p < 4; p++)
                LDSM4(b[2*p][0], b[2*p][1], b[2*p+1][0], b[2*p+1][1], bb + bLb[p] + ko);
#pragma unroll
            for (int mb = 0; mb < 4; mb++)
#pragma unroll
                for (int nb = 0; nb < 8; nb++)
                    mma16h(acc[mb][nb], a[mb], b[nb]);
        }
    }

    // non-atomic scatter into per-slot combine buffers
#pragma unroll
    for (int mb = 0; mb < 4; mb++) {
        int r0 = row0 + wm * 64 + mb * 16 + g;
        int r1 = r0 + 8;
        int pk0 = (r0 < n) ? g_tok[e][r0] : -1;
        int pk1 = (r1 < n) ? g_tok[e][r1] : -1;
        float* d0 = (pk0 >= 0)
            ? &g_comb[((size_t)(pk0 >> 16) * T_TOK + (pk0 & 0xFFFF)) * H_DIM] : 0;
        float* d1 = (pk1 >= 0)
            ? &g_comb[((size_t)(pk1 >> 16) * T_TOK + (pk1 & 0xFFFF)) * H_DIM] : 0;
#pragma unroll
        for (int nb = 0; nb < 8; nb++) {
            int col = h0 + wn * 64 + nb * 8 + 2 * t;
            if (d0) { float2 v; v.x = acc[mb][nb][0]; v.y = acc[mb][nb][1];
                      *(float2*)&d0[col] = v; }
            if (d1) { float2 v; v.x = acc[mb][nb][2]; v.y = acc[mb][nb][3];
                      *(float2*)&d1[col] = v; }
        }
    }
}

// ---------------- combine: out = w0*comb0 + w1*comb1 ------------------------
__global__ void combine_kernel(float* __restrict__ out) {
    int idx = blockIdx.x * blockDim.x + threadIdx.x;
    const int nq = T_TOK * H_DIM / 4;
    if (idx >= nq) return;
    int tk = idx / (H_DIM / 4);
    float w0 = g_wslot[tk], w1 = g_wslot[T_TOK + tk];
    float4 v0 = ((const float4*)g_comb)[idx];
    float4 v1 = ((const float4*)g_comb)[(size_t)(T_TOK * H_DIM / 4) + idx];
    float4 r;
    r.x = w0 * v0.x + w1 * v1.x;
    r.y = w0 * v0.y + w1 * v1.y;
    r.z = w0 * v0.z + w1 * v1.z;
    r.w = w0 * v0.w + w1 * v1.w;
    ((float4*)out)[idx] = r;
}

// ---------------- launch -----------------------------------------------------
extern "C" void kernel_launch(void* const* d_in, const int* in_sizes, int n_in,
                              void* d_out, int out_size) {
    const float* x  = (const float*)d_in[0];  // [2,2048,1024]
    const float* gw = (const float*)d_in[1];  // [8,1024]
    const float* w1 = (const float*)d_in[2];  // [8,2048,1024]
    const float* w2 = (const float*)d_in[3];  // [8,1024,2048]
    const float* w3 = (const float*)d_in[4];  // [8,2048,1024]
    float* out = (float*)d_out;

    const size_t final_elems = (size_t)T_TOK * H_DIM;
    int write_logits = ((size_t)out_size >= final_elems + (size_t)T_TOK * NEXP) ? 1 : 0;
    float* logits = out + final_elems;

    const int dynsm = STAGES * 36864;   // 110592 per CTA -> 2 CTAs/SM
    cudaFuncSetAttribute(gemm1_tc, cudaFuncAttributeMaxDynamicSharedMemorySize, dynsm);
    cudaFuncSetAttribute(gemm2_tc, cudaFuncAttributeMaxDynamicSharedMemorySize, dynsm);

    const size_t wq = (size_t)NEXP * FF_DIM * H_DIM / 4;
    round_weights_kernel<<<(int)((wq + 255) / 256), 256>>>(w1, w2, w3);
    router_kernel<<<T_TOK / 8, 256>>>(x, gw, logits, write_logits);

    dim3 g1(FF_DIM / 64, T_TOK / 128, NEXP);   // (32, 32, 8)
    gemm1_tc<<<g1, 128, dynsm>>>(x);

    dim3 g2(H_DIM / 128, T_TOK / 128, NEXP);   // (8, 32, 8)
    gemm2_tc<<<g2, 128, dynsm>>>(x);

    combine_kernel<<<(T_TOK * H_DIM / 4 + 255) / 256, 256>>>(out);
}

// round 12
// speedup vs baseline: 1.6850x; 1.0041x over previous
#include <cuda_runtime.h>
#include <cuda_fp16.h>
#include <math.h>
#include <stdint.h>

#define T_TOK 4096
#define H_DIM 1024
#define FF_DIM 2048
#define NEXP 8
#define SSH 72           // padded row stride in halves (144 B)
#define STAGES 3
#define WBLK 16384       // weight-conversion blocks in prolog

// ---------------- device scratch (allocation-guard safe) --------------------
__device__ int      g_counts[NEXP];              // zero-init; combine re-zeros
__device__ int      g_tok[NEXP][T_TOK];          // packed: tok | slot<<16
__device__ float    g_wslot[2 * T_TOK];
__device__ __half   g_innerh[(size_t)NEXP * T_TOK * FF_DIM];  // 128 MB
__device__ float    g_comb[(size_t)2 * T_TOK * H_DIM];        // 32 MB
__device__ __half   g_w1h[(size_t)NEXP * FF_DIM * H_DIM];     // 32 MB
__device__ __half   g_w3h[(size_t)NEXP * FF_DIM * H_DIM];     // 32 MB
__device__ __half   g_w2h[(size_t)NEXP * H_DIM * FF_DIM];     // 32 MB
__device__ __half   g_xh[(size_t)T_TOK * H_DIM];              // 8 MB

// ---------------- helpers ----------------------------------------------------
__device__ __forceinline__ uint32_t h2u(float a, float b) {
    __half2 h = __floats2half2_rn(a, b);
    return *(uint32_t*)&h;
}
__device__ __forceinline__ uint2 cvt4h(float4 v) {
    uint2 u; u.x = h2u(v.x, v.y); u.y = h2u(v.z, v.w); return u;
}
__device__ __forceinline__ void mma16h(float* c, const uint32_t* a, const uint32_t* b) {
    asm volatile(
        "mma.sync.aligned.m16n8k16.row.col.f32.f16.f16.f32 "
        "{%0,%1,%2,%3}, {%4,%5,%6,%7}, {%8,%9}, {%0,%1,%2,%3};"
        : "+f"(c[0]), "+f"(c[1]), "+f"(c[2]), "+f"(c[3])
        : "r"(a[0]), "r"(a[1]), "r"(a[2]), "r"(a[3]), "r"(b[0]), "r"(b[1]));
}
#define LDSM4(r0, r1, r2, r3, addr) \
    asm volatile("ldmatrix.sync.aligned.m8n8.x4.shared.b16 {%0,%1,%2,%3}, [%4];" \
                 : "=r"(r0), "=r"(r1), "=r"(r2), "=r"(r3) : "r"(addr))
#define CP16(dst, src) \
    asm volatile("cp.async.cg.shared.global [%0], [%1], 16;" \
                 :: "r"(dst), "l"(src) : "memory")
#define CPCOMMIT() asm volatile("cp.async.commit_group;" ::: "memory")
#define CPWAIT1()  asm volatile("cp.async.wait_group 1;" ::: "memory")
#define CPWAIT0()  asm volatile("cp.async.wait_group 0;" ::: "memory")

// ---------------- prolog: weight cvt (blocks < WBLK) + router (rest) --------
// NOTE: g_counts is NOT zeroed here — it is re-zeroed by combine_kernel at the
// end of every invocation (and __device__ globals are zero-initialized), so
// the router always sees counts==0 with no intra-kernel race.
__global__ void prolog_kernel(const float* __restrict__ w1,
                              const float* __restrict__ w2,
                              const float* __restrict__ w3,
                              const float* __restrict__ x,
                              const float* __restrict__ gw,
                              float* __restrict__ logits_out,
                              int write_logits) {
    if (blockIdx.x < WBLK) {
        size_t i = (size_t)blockIdx.x * blockDim.x + threadIdx.x;
        ((uint2*)g_w1h)[i] = cvt4h(((const float4*)w1)[i]);
        ((uint2*)g_w3h)[i] = cvt4h(((const float4*)w3)[i]);
        ((uint2*)g_w2h)[i] = cvt4h(((const float4*)w2)[i]);
        return;
    }

    int warp = (((int)blockIdx.x - WBLK) * blockDim.x + threadIdx.x) >> 5;
    int lane = threadIdx.x & 31;
    if (warp >= T_TOK) return;

    const float* xr = x + (size_t)warp * H_DIM;

    for (int i = lane; i < H_DIM / 2; i += 32) {
        float2 v = ((const float2*)xr)[i];
        ((uint32_t*)g_xh)[(size_t)warp * (H_DIM / 2) + i] = h2u(v.x, v.y);
    }

    float xv[32];
#pragma unroll
    for (int i = 0; i < 32; i++) xv[i] = xr[lane + 32 * i];

    float lg[NEXP];
#pragma unroll
    for (int e = 0; e < NEXP; e++) {
        const float* g = gw + (size_t)e * H_DIM;
        float s = 0.f;
#pragma unroll
        for (int i = 0; i < 32; i++) s += xv[i] * g[lane + 32 * i];
#pragma unroll
        for (int o = 16; o > 0; o >>= 1) s += __shfl_xor_sync(0xffffffffu, s, o);
        lg[e] = s;
    }

    if (lane == 0) {
        if (write_logits) {
#pragma unroll
            for (int e = 0; e < NEXP; e++)
                logits_out[(size_t)warp * NEXP + e] = lg[e];
        }
        float mx = lg[0];
#pragma unroll
        for (int e = 1; e < NEXP; e++) mx = fmaxf(mx, lg[e]);
        float p[NEXP], sum = 0.f;
#pragma unroll
        for (int e = 0; e < NEXP; e++) { p[e] = expf(lg[e] - mx); sum += p[e]; }
#pragma unroll
        for (int e = 0; e < NEXP; e++) p[e] /= sum;
        int i1 = 0;
#pragma unroll
        for (int e = 1; e < NEXP; e++) if (p[e] > p[i1]) i1 = e;
        int i2 = (i1 == 0) ? 1 : 0;
#pragma unroll
        for (int e = 0; e < NEXP; e++) if (e != i1 && p[e] > p[i2]) i2 = e;
        float s2 = p[i1] + p[i2];
        int pos = atomicAdd(&g_counts[i1], 1);
        g_tok[i1][pos] = warp;                 // slot 0
        pos = atomicAdd(&g_counts[i2], 1);
        g_tok[i2][pos] = warp | 0x10000;       // slot 1
        g_wslot[warp]         = p[i1] / s2;
        g_wslot[T_TOK + warp] = p[i2] / s2;
    }
}

// ---------------- GEMM1: inner = silu(Xg@W1^T)*(Xg@W3^T), fp16 MMA ----------
// block 128M x 32N-dual(64 eff) x 64K; 4 warps = 2M x 2N; warp tile 64x32 per
// matrix. 128 threads, 2 CTAs/SM, 3-stage cp.async ring. (round-11, frozen)
#define G1_SZ   36864u           // (128+64+64)*144
#define G1_B1O  18432u           // 128*144
#define G1_B3O  27648u           // 192*144

__global__ void __launch_bounds__(128, 2)
gemm1_tc(const float* __restrict__ dummy) {
    extern __shared__ __align__(16) char smc[];
    const uint32_t sbase = (uint32_t)__cvta_generic_to_shared(smc);

    const int e = blockIdx.z;
    const int n = g_counts[e];
    const int row0 = blockIdx.y * 128;
    if (row0 >= n) return;
    const int ff0 = blockIdx.x * 64;

    const int tid = threadIdx.x;
    const int wid = tid >> 5, lane = tid & 31;
    const int wm = wid & 1, wn = wid >> 1;        // 2M x 2N
    const int g = lane >> 2, t = lane & 3;

    const __half* apt[8];
#pragma unroll
    for (int i = 0; i < 8; i++) {
        int r = row0 + (tid >> 3) + 16 * i;
        int tok = (r < n) ? (g_tok[e][r] & 0xFFFF) : 0;
        apt[i] = g_xh + (size_t)tok * H_DIM + (tid & 7) * 8;
    }
    const __half* b1p0 = g_w1h + ((size_t)e * FF_DIM + ff0 + (tid >> 3)) * H_DIM + (tid & 7) * 8;
    const __half* b3p0 = g_w3h + ((size_t)e * FF_DIM + ff0 + (tid >> 3)) * H_DIM + (tid & 7) * 8;
    const uint32_t off0 = (uint32_t)((tid >> 3) * SSH + (tid & 7) * 8) * 2u;
    const uint32_t ostep = 16u * SSH * 2u;

    auto issue = [&](int s) {
        uint32_t base = sbase + (uint32_t)(s % STAGES) * G1_SZ;
        int k0 = s * 64;
        uint32_t o = off0;
#pragma unroll
        for (int i = 0; i < 8; i++) { CP16(base + o, apt[i] + k0); o += ostep; }
        o = off0;
#pragma unroll
        for (int i = 0; i < 4; i++) {
            CP16(base + G1_B1O + o, b1p0 + (size_t)16 * i * H_DIM + k0);
            CP16(base + G1_B3O + o, b3p0 + (size_t)16 * i * H_DIM + k0);
            o += ostep;
        }
        CPCOMMIT();
    };

    float acc1[4][4][4], acc3[4][4][4];
#pragma unroll
    for (int mb = 0; mb < 4; mb++)
#pragma unroll
        for (int nb = 0; nb < 4; nb++)
#pragma unroll
            for (int j = 0; j < 4; j++) { acc1[mb][nb][j] = 0.f; acc3[mb][nb][j] = 0.f; }

    uint32_t aLb0 = (uint32_t)((wm * 64 + (lane & 15)) * SSH) * 2u
                  + (uint32_t)(lane >> 4) * 16u;
    const uint32_t aMstep = 16u * SSH * 2u;
    uint32_t bLb[2];
#pragma unroll
    for (int p = 0; p < 2; p++)
        bLb[p] = (uint32_t)((wn * 32 + p * 16 + ((lane >> 4) << 3) + (lane & 7)) * SSH) * 2u
               + (uint32_t)((lane >> 3) & 1) * 16u;

    issue(0); issue(1);

    const int NIT = H_DIM / 64;     // 16
    for (int it = 0; it < NIT; ++it) {
        if (it + 1 < NIT) CPWAIT1(); else CPWAIT0();
        __syncthreads();
        if (it + STAGES - 1 < NIT) issue(it + STAGES - 1);

        const uint32_t sb  = sbase + (uint32_t)(it % STAGES) * G1_SZ;
        const uint32_t b1b = sb + G1_B1O;
        const uint32_t b3b = sb + G1_B3O;

#pragma unroll
        for (int kk = 0; kk < 4; kk++) {
            const uint32_t ko = (uint32_t)kk * 32u;
            uint32_t a[4][4], b1[4][2], b3[4][2];
#pragma unroll
            for (int mb = 0; mb < 4; mb++)
                LDSM4(a[mb][0], a[mb][1], a[mb][2], a[mb][3],
                      sb + aLb0 + (uint32_t)mb * aMstep + ko);
#pragma unroll
            for (int p = 0; p < 2; p++) {
                LDSM4(b1[2*p][0], b1[2*p][1], b1[2*p+1][0], b1[2*p+1][1], b1b + bLb[p] + ko);
                LDSM4(b3[2*p][0], b3[2*p][1], b3[2*p+1][0], b3[2*p+1][1], b3b + bLb[p] + ko);
            }
#pragma unroll
            for (int mb = 0; mb < 4; mb++)
#pragma unroll
                for (int nb = 0; nb < 4; nb++) {
                    mma16h(acc1[mb][nb], a[mb], b1[nb]);
                    mma16h(acc3[mb][nb], a[mb], b3[nb]);
                }
        }
    }

    // fused SwiGLU epilogue -> g_innerh
#pragma unroll
    for (int mb = 0; mb < 4; mb++) {
        int r0 = row0 + wm * 64 + mb * 16 + g;
        int r1 = r0 + 8;
#pragma unroll
        for (int nb = 0; nb < 4; nb++) {
            int col = ff0 + wn * 32 + nb * 8 + 2 * t;
            if (r0 < n) {
                float a0 = acc1[mb][nb][0], a1 = acc1[mb][nb][1];
                float v0 = (a0 / (1.f + expf(-a0))) * acc3[mb][nb][0];
                float v1 = (a1 / (1.f + expf(-a1))) * acc3[mb][nb][1];
                *(uint32_t*)&g_innerh[((size_t)e * T_TOK + r0) * FF_DIM + col] = h2u(v0, v1);
            }
            if (r1 < n) {
                float a2 = acc1[mb][nb][2], a3 = acc1[mb][nb][3];
                float v2 = (a2 / (1.f + expf(-a2))) * acc3[mb][nb][2];
                float v3 = (a3 / (1.f + expf(-a3))) * acc3[mb][nb][3];
                *(uint32_t*)&g_innerh[((size_t)e * T_TOK + r1) * FF_DIM + col] = h2u(v2, v3);
            }
        }
    }
}

// ---------------- GEMM2: comb[slot][tok] = inner @ W2^T, fp16 MMA -----------
// block 128M x 128N x 64K; 4 warps = 2M x 2N; warp tile 64x64.
// 128 threads, 2 CTAs/SM, 3-stage cp.async ring. (round-11, frozen)
#define G2_SZ  36864u            // (128+128)*144
#define G2_BO  18432u            // 128*144

__global__ void __launch_bounds__(128, 2)
gemm2_tc(const float* __restrict__ dummy) {
    extern __shared__ __align__(16) char smc[];
    const uint32_t sbase = (uint32_t)__cvta_generic_to_shared(smc);

    const int e = blockIdx.z;
    const int n = g_counts[e];
    const int row0 = blockIdx.y * 128;
    if (row0 >= n) return;
    const int h0 = blockIdx.x * 128;

    const int tid = threadIdx.x;
    const int wid = tid >> 5, lane = tid & 31;
    const int wm = wid & 1, wn = wid >> 1;        // 2M x 2N
    const int g = lane >> 2, t = lane & 3;

    const __half* ap0 = g_innerh + ((size_t)e * T_TOK + row0 + (tid >> 3)) * FF_DIM + (tid & 7) * 8;
    const __half* bp0 = g_w2h + ((size_t)e * H_DIM + h0 + (tid >> 3)) * FF_DIM + (tid & 7) * 8;
    const uint32_t off0 = (uint32_t)((tid >> 3) * SSH + (tid & 7) * 8) * 2u;
    const uint32_t ostep = 16u * SSH * 2u;
    const size_t pstep = (size_t)16 * FF_DIM;

    auto issue = [&](int s) {
        uint32_t base = sbase + (uint32_t)(s % STAGES) * G2_SZ;
        int k0 = s * 64;
        const __half* ap = ap0 + k0;
        const __half* bp = bp0 + k0;
        uint32_t o = off0;
#pragma unroll
        for (int i = 0; i < 8; i++) {
            CP16(base + o, ap);
            CP16(base + G2_BO + o, bp);
            ap += pstep; bp += pstep; o += ostep;
        }
        CPCOMMIT();
    };

    float acc[4][8][4];
#pragma unroll
    for (int mb = 0; mb < 4; mb++)
#pragma unroll
        for (int nb = 0; nb < 8; nb++)
#pragma unroll
            for (int j = 0; j < 4; j++) acc[mb][nb][j] = 0.f;

    uint32_t aLb0 = (uint32_t)((wm * 64 + (lane & 15)) * SSH) * 2u
                  + (uint32_t)(lane >> 4) * 16u;
    const uint32_t aMstep = 16u * SSH * 2u;
    uint32_t bLb[4];
#pragma unroll
    for (int p = 0; p < 4; p++)
        bLb[p] = (uint32_t)((wn * 64 + p * 16 + ((lane >> 4) << 3) + (lane & 7)) * SSH) * 2u
               + (uint32_t)((lane >> 3) & 1) * 16u;

    issue(0); issue(1);

    const int NIT = FF_DIM / 64;    // 32
    for (int it = 0; it < NIT; ++it) {
        if (it + 1 < NIT) CPWAIT1(); else CPWAIT0();
        __syncthreads();
        if (it + STAGES - 1 < NIT) issue(it + STAGES - 1);

        const uint32_t sb = sbase + (uint32_t)(it % STAGES) * G2_SZ;
        const uint32_t bb = sb + G2_BO;

#pragma unroll
        for (int kk = 0; kk < 4; kk++) {
            const uint32_t ko = (uint32_t)kk * 32u;
            uint32_t a[4][4], b[8][2];
#pragma unroll
            for (int mb = 0; mb < 4; mb++)
                LDSM4(a[mb][0], a[mb][1], a[mb][2], a[mb][3],
                      sb + aLb0 + (uint32_t)mb * aMstep + ko);
#pragma unroll
            for (int p = 0; p < 4; p++)
                LDSM4(b[2*p][0], b[2*p][1], b[2*p+1][0], b[2*p+1][1], bb + bLb[p] + ko);
#pragma unroll
            for (int mb = 0; mb < 4; mb++)
#pragma unroll
                for (int nb = 0; nb < 8; nb++)
                    mma16h(acc[mb][nb], a[mb], b[nb]);
        }
    }

    // non-atomic scatter into per-slot combine buffers
#pragma unroll
    for (int mb = 0; mb < 4; mb++) {
        int r0 = row0 + wm * 64 + mb * 16 + g;
        int r1 = r0 + 8;
        int pk0 = (r0 < n) ? g_tok[e][r0] : -1;
        int pk1 = (r1 < n) ? g_tok[e][r1] : -1;
        float* d0 = (pk0 >= 0)
            ? &g_comb[((size_t)(pk0 >> 16) * T_TOK + (pk0 & 0xFFFF)) * H_DIM] : 0;
        float* d1 = (pk1 >= 0)
            ? &g_comb[((size_t)(pk1 >> 16) * T_TOK + (pk1 & 0xFFFF)) * H_DIM] : 0;
#pragma unroll
        for (int nb = 0; nb < 8; nb++) {
            int col = h0 + wn * 64 + nb * 8 + 2 * t;
            if (d0) { float2 v; v.x = acc[mb][nb][0]; v.y = acc[mb][nb][1];
                      *(float2*)&d0[col] = v; }
            if (d1) { float2 v; v.x = acc[mb][nb][2]; v.y = acc[mb][nb][3];
                      *(float2*)&d1[col] = v; }
        }
    }
}

// ---------------- combine: out = w0*comb0 + w1*comb1; re-zero counts --------
__global__ void combine_kernel(float* __restrict__ out) {
    int idx = blockIdx.x * blockDim.x + threadIdx.x;
    const int nq = T_TOK * H_DIM / 4;
    if (blockIdx.x == 0 && threadIdx.x < NEXP)
        g_counts[threadIdx.x] = 0;           // reset for the NEXT invocation
    if (idx >= nq) return;
    int tk = idx / (H_DIM / 4);
    float w0 = g_wslot[tk], w1 = g_wslot[T_TOK + tk];
    float4 v0 = ((const float4*)g_comb)[idx];
    float4 v1 = ((const float4*)g_comb)[(size_t)(T_TOK * H_DIM / 4) + idx];
    float4 r;
    r.x = w0 * v0.x + w1 * v1.x;
    r.y = w0 * v0.y + w1 * v1.y;
    r.z = w0 * v0.z + w1 * v1.z;
    r.w = w0 * v0.w + w1 * v1.w;
    ((float4*)out)[idx] = r;
}

// ---------------- launch -----------------------------------------------------
extern "C" void kernel_launch(void* const* d_in, const int* in_sizes, int n_in,
                              void* d_out, int out_size) {
    const float* x  = (const float*)d_in[0];  // [2,2048,1024]
    const float* gw = (const float*)d_in[1];  // [8,1024]
    const float* w1 = (const float*)d_in[2];  // [8,2048,1024]
    const float* w2 = (const float*)d_in[3];  // [8,1024,2048]
    const float* w3 = (const float*)d_in[4];  // [8,2048,1024]
    float* out = (float*)d_out;

    const size_t final_elems = (size_t)T_TOK * H_DIM;
    int write_logits = ((size_t)out_size >= final_elems + (size_t)T_TOK * NEXP) ? 1 : 0;
    float* logits = out + final_elems;

    const int dynsm = STAGES * 36864;   // 110592 per CTA -> 2 CTAs/SM
    cudaFuncSetAttribute(gemm1_tc, cudaFuncAttributeMaxDynamicSharedMemorySize, dynsm);
    cudaFuncSetAttribute(gemm2_tc, cudaFuncAttributeMaxDynamicSharedMemorySize, dynsm);

    // prolog: 16384 weight-cvt blocks + 512 router blocks (8 tokens each)
    prolog_kernel<<<WBLK + T_TOK / 8, 256>>>(w1, w2, w3, x, gw, logits, write_logits);

    dim3 g1(FF_DIM / 64, T_TOK / 128, NEXP);   // (32, 32, 8)
    gemm1_tc<<<g1, 128, dynsm>>>(x);

    dim3 g2(H_DIM / 128, T_TOK / 128, NEXP);   // (8, 32, 8)
    gemm2_tc<<<g2, 128, dynsm>>>(x);

    combine_kernel<<<(T_TOK * H_DIM / 4 + 255) / 256, 256>>>(out);
}

// round 13
// speedup vs baseline: 1.7255x; 1.0241x over previous
#include <cuda_runtime.h>
#include <cuda_fp16.h>
#include <math.h>
#include <stdint.h>

#define T_TOK 4096
#define H_DIM 1024
#define FF_DIM 2048
#define NEXP 8
#define SSH 72           // padded row stride in halves (144 B)
#define STAGES 3
#define WBLK 16384       // w1/w3-conversion blocks in prolog
#define G1T  8192        // gemm1 GEMM tiles (32 ff x 32 row x 8 e)
#define W2BLK 8192       // w2-conversion blocks appended to gemm1 grid

// ---------------- device scratch (allocation-guard safe) --------------------
__device__ int      g_counts[NEXP];              // zero-init; combine re-zeros
__device__ int      g_tok[NEXP][T_TOK];          // packed: tok | slot<<16
__device__ float    g_wslot[2 * T_TOK];
__device__ __half   g_innerh[(size_t)NEXP * T_TOK * FF_DIM];  // 128 MB
__device__ float    g_comb[(size_t)2 * T_TOK * H_DIM];        // 32 MB
__device__ __half   g_w1h[(size_t)NEXP * FF_DIM * H_DIM];     // 32 MB
__device__ __half   g_w3h[(size_t)NEXP * FF_DIM * H_DIM];     // 32 MB
__device__ __half   g_w2h[(size_t)NEXP * H_DIM * FF_DIM];     // 32 MB
__device__ __half   g_xh[(size_t)T_TOK * H_DIM];              // 8 MB

// ---------------- helpers ----------------------------------------------------
__device__ __forceinline__ uint32_t h2u(float a, float b) {
    __half2 h = __floats2half2_rn(a, b);
    return *(uint32_t*)&h;
}
__device__ __forceinline__ uint2 cvt4h(float4 v) {
    uint2 u; u.x = h2u(v.x, v.y); u.y = h2u(v.z, v.w); return u;
}
__device__ __forceinline__ void mma16h(float* c, const uint32_t* a, const uint32_t* b) {
    asm volatile(
        "mma.sync.aligned.m16n8k16.row.col.f32.f16.f16.f32 "
        "{%0,%1,%2,%3}, {%4,%5,%6,%7}, {%8,%9}, {%0,%1,%2,%3};"
        : "+f"(c[0]), "+f"(c[1]), "+f"(c[2]), "+f"(c[3])
        : "r"(a[0]), "r"(a[1]), "r"(a[2]), "r"(a[3]), "r"(b[0]), "r"(b[1]));
}
#define LDSM4(r0, r1, r2, r3, addr) \
    asm volatile("ldmatrix.sync.aligned.m8n8.x4.shared.b16 {%0,%1,%2,%3}, [%4];" \
                 : "=r"(r0), "=r"(r1), "=r"(r2), "=r"(r3) : "r"(addr))
#define CP16(dst, src) \
    asm volatile("cp.async.cg.shared.global [%0], [%1], 16;" \
                 :: "r"(dst), "l"(src) : "memory")
#define CPCOMMIT() asm volatile("cp.async.commit_group;" ::: "memory")
#define CPWAIT1()  asm volatile("cp.async.wait_group 1;" ::: "memory")
#define CPWAIT0()  asm volatile("cp.async.wait_group 0;" ::: "memory")

// ---------------- prolog: w1/w3 cvt (blocks < WBLK) + router (rest) ---------
// g_counts is re-zeroed by combine_kernel at the end of every invocation
// (and __device__ globals are zero-initialized), so the router always sees
// counts==0 with no intra-kernel race.
__global__ void prolog_kernel(const float* __restrict__ w1,
                              const float* __restrict__ w3,
                              const float* __restrict__ x,
                              const float* __restrict__ gw,
                              float* __restrict__ logits_out,
                              int write_logits) {
    if (blockIdx.x < WBLK) {
        size_t i = (size_t)blockIdx.x * blockDim.x + threadIdx.x;
        ((uint2*)g_w1h)[i] = cvt4h(((const float4*)w1)[i]);
        ((uint2*)g_w3h)[i] = cvt4h(((const float4*)w3)[i]);
        return;
    }

    int warp = (((int)blockIdx.x - WBLK) * blockDim.x + threadIdx.x) >> 5;
    int lane = threadIdx.x & 31;
    if (warp >= T_TOK) return;

    const float* xr = x + (size_t)warp * H_DIM;

    for (int i = lane; i < H_DIM / 2; i += 32) {
        float2 v = ((const float2*)xr)[i];
        ((uint32_t*)g_xh)[(size_t)warp * (H_DIM / 2) + i] = h2u(v.x, v.y);
    }

    float xv[32];
#pragma unroll
    for (int i = 0; i < 32; i++) xv[i] = xr[lane + 32 * i];

    float lg[NEXP];
#pragma unroll
    for (int e = 0; e < NEXP; e++) {
        const float* g = gw + (size_t)e * H_DIM;
        float s = 0.f;
#pragma unroll
        for (int i = 0; i < 32; i++) s += xv[i] * g[lane + 32 * i];
#pragma unroll
        for (int o = 16; o > 0; o >>= 1) s += __shfl_xor_sync(0xffffffffu, s, o);
        lg[e] = s;
    }

    if (lane == 0) {
        if (write_logits) {
#pragma unroll
            for (int e = 0; e < NEXP; e++)
                logits_out[(size_t)warp * NEXP + e] = lg[e];
        }
        float mx = lg[0];
#pragma unroll
        for (int e = 1; e < NEXP; e++) mx = fmaxf(mx, lg[e]);
        float p[NEXP], sum = 0.f;
#pragma unroll
        for (int e = 0; e < NEXP; e++) { p[e] = expf(lg[e] - mx); sum += p[e]; }
#pragma unroll
        for (int e = 0; e < NEXP; e++) p[e] /= sum;
        int i1 = 0;
#pragma unroll
        for (int e = 1; e < NEXP; e++) if (p[e] > p[i1]) i1 = e;
        int i2 = (i1 == 0) ? 1 : 0;
#pragma unroll
        for (int e = 0; e < NEXP; e++) if (e != i1 && p[e] > p[i2]) i2 = e;
        float s2 = p[i1] + p[i2];
        int pos = atomicAdd(&g_counts[i1], 1);
        g_tok[i1][pos] = warp;                 // slot 0
        pos = atomicAdd(&g_counts[i2], 1);
        g_tok[i2][pos] = warp | 0x10000;       // slot 1
        g_wslot[warp]         = p[i1] / s2;
        g_wslot[T_TOK + warp] = p[i2] / s2;
    }
}

// ---------------- GEMM1 (+ appended w2 conversion blocks) -------------------
// GEMM: block 128M x 32N-dual(64 eff) x 64K; 4 warps = 2M x 2N; warp tile
// 64x32 per matrix; 128 threads, 2 CTAs/SM, 3-stage cp.async ring (frozen).
// Flat 1D grid: blocks [0, G1T) are GEMM tiles in the same (bx,by,e) order
// as the old 3D launch; blocks [G1T, G1T+W2BLK) convert w2 fp32->fp16 using
// gemm1's idle DRAM bandwidth. Kernel boundary orders w2h before gemm2.
#define G1_SZ   36864u           // (128+64+64)*144
#define G1_B1O  18432u           // 128*144
#define G1_B3O  27648u           // 192*144

__global__ void __launch_bounds__(128, 2)
gemm1_tc(const float* __restrict__ w2src) {
    extern __shared__ __align__(16) char smc[];
    const uint32_t sbase = (uint32_t)__cvta_generic_to_shared(smc);

    if (blockIdx.x >= G1T) {
        // w2 conversion: 8192 blocks x 128 thr x 4 float4
        size_t i = (size_t)(blockIdx.x - G1T) * 128 + threadIdx.x;
        const float4* src = (const float4*)w2src;
#pragma unroll
        for (int j = 0; j < 4; j++) {
            size_t idx = i + (size_t)j * (W2BLK * 128);
            ((uint2*)g_w2h)[idx] = cvt4h(src[idx]);
        }
        return;
    }

    const int f = blockIdx.x;
    const int e = f >> 10;              // 1024 tiles per expert
    const int row0 = ((f >> 5) & 31) * 128;
    const int ff0 = (f & 31) * 64;
    const int n = g_counts[e];
    if (row0 >= n) return;

    const int tid = threadIdx.x;
    const int wid = tid >> 5, lane = tid & 31;
    const int wm = wid & 1, wn = wid >> 1;        // 2M x 2N
    const int g = lane >> 2, t = lane & 3;

    const __half* apt[8];
#pragma unroll
    for (int i = 0; i < 8; i++) {
        int r = row0 + (tid >> 3) + 16 * i;
        int tok = (r < n) ? (g_tok[e][r] & 0xFFFF) : 0;
        apt[i] = g_xh + (size_t)tok * H_DIM + (tid & 7) * 8;
    }
    const __half* b1p0 = g_w1h + ((size_t)e * FF_DIM + ff0 + (tid >> 3)) * H_DIM + (tid & 7) * 8;
    const __half* b3p0 = g_w3h + ((size_t)e * FF_DIM + ff0 + (tid >> 3)) * H_DIM + (tid & 7) * 8;
    const uint32_t off0 = (uint32_t)((tid >> 3) * SSH + (tid & 7) * 8) * 2u;
    const uint32_t ostep = 16u * SSH * 2u;

    auto issue = [&](int s) {
        uint32_t base = sbase + (uint32_t)(s % STAGES) * G1_SZ;
        int k0 = s * 64;
        uint32_t o = off0;
#pragma unroll
        for (int i = 0; i < 8; i++) { CP16(base + o, apt[i] + k0); o += ostep; }
        o = off0;
#pragma unroll
        for (int i = 0; i < 4; i++) {
            CP16(base + G1_B1O + o, b1p0 + (size_t)16 * i * H_DIM + k0);
            CP16(base + G1_B3O + o, b3p0 + (size_t)16 * i * H_DIM + k0);
            o += ostep;
        }
        CPCOMMIT();
    };

    float acc1[4][4][4], acc3[4][4][4];
#pragma unroll
    for (int mb = 0; mb < 4; mb++)
#pragma unroll
        for (int nb = 0; nb < 4; nb++)
#pragma unroll
            for (int j = 0; j < 4; j++) { acc1[mb][nb][j] = 0.f; acc3[mb][nb][j] = 0.f; }

    uint32_t aLb0 = (uint32_t)((wm * 64 + (lane & 15)) * SSH) * 2u
                  + (uint32_t)(lane >> 4) * 16u;
    const uint32_t aMstep = 16u * SSH * 2u;
    uint32_t bLb[2];
#pragma unroll
    for (int p = 0; p < 2; p++)
        bLb[p] = (uint32_t)((wn * 32 + p * 16 + ((lane >> 4) << 3) + (lane & 7)) * SSH) * 2u
               + (uint32_t)((lane >> 3) & 1) * 16u;

    issue(0); issue(1);

    const int NIT = H_DIM / 64;     // 16
    for (int it = 0; it < NIT; ++it) {
        if (it + 1 < NIT) CPWAIT1(); else CPWAIT0();
        __syncthreads();
        if (it + STAGES - 1 < NIT) issue(it + STAGES - 1);

        const uint32_t sb  = sbase + (uint32_t)(it % STAGES) * G1_SZ;
        const uint32_t b1b = sb + G1_B1O;
        const uint32_t b3b = sb + G1_B3O;

#pragma unroll
        for (int kk = 0; kk < 4; kk++) {
            const uint32_t ko = (uint32_t)kk * 32u;
            uint32_t a[4][4], b1[4][2], b3[4][2];
#pragma unroll
            for (int mb = 0; mb < 4; mb++)
                LDSM4(a[mb][0], a[mb][1], a[mb][2], a[mb][3],
                      sb + aLb0 + (uint32_t)mb * aMstep + ko);
#pragma unroll
            for (int p = 0; p < 2; p++) {
                LDSM4(b1[2*p][0], b1[2*p][1], b1[2*p+1][0], b1[2*p+1][1], b1b + bLb[p] + ko);
                LDSM4(b3[2*p][0], b3[2*p][1], b3[2*p+1][0], b3[2*p+1][1], b3b + bLb[p] + ko);
            }
#pragma unroll
            for (int mb = 0; mb < 4; mb++)
#pragma unroll
                for (int nb = 0; nb < 4; nb++) {
                    mma16h(acc1[mb][nb], a[mb], b1[nb]);
                    mma16h(acc3[mb][nb], a[mb], b3[nb]);
                }
        }
    }

    // fused SwiGLU epilogue -> g_innerh
#pragma unroll
    for (int mb = 0; mb < 4; mb++) {
        int r0 = row0 + wm * 64 + mb * 16 + g;
        int r1 = r0 + 8;
#pragma unroll
        for (int nb = 0; nb < 4; nb++) {
            int col = ff0 + wn * 32 + nb * 8 + 2 * t;
            if (r0 < n) {
                float a0 = acc1[mb][nb][0], a1 = acc1[mb][nb][1];
                float v0 = (a0 / (1.f + expf(-a0))) * acc3[mb][nb][0];
                float v1 = (a1 / (1.f + expf(-a1))) * acc3[mb][nb][1];
                *(uint32_t*)&g_innerh[((size_t)e * T_TOK + r0) * FF_DIM + col] = h2u(v0, v1);
            }
            if (r1 < n) {
                float a2 = acc1[mb][nb][2], a3 = acc1[mb][nb][3];
                float v2 = (a2 / (1.f + expf(-a2))) * acc3[mb][nb][2];
                float v3 = (a3 / (1.f + expf(-a3))) * acc3[mb][nb][3];
                *(uint32_t*)&g_innerh[((size_t)e * T_TOK + r1) * FF_DIM + col] = h2u(v2, v3);
            }
        }
    }
}

// ---------------- GEMM2: comb[slot][tok] = inner @ W2^T, fp16 MMA -----------
// block 128M x 128N x 64K; 4 warps = 2M x 2N; warp tile 64x64.
// 128 threads, 2 CTAs/SM, 3-stage cp.async ring. (round-11, frozen)
#define G2_SZ  36864u            // (128+128)*144
#define G2_BO  18432u            // 128*144

__global__ void __launch_bounds__(128, 2)
gemm2_tc(const float* __restrict__ dummy) {
    extern __shared__ __align__(16) char smc[];
    const uint32_t sbase = (uint32_t)__cvta_generic_to_shared(smc);

    const int e = blockIdx.z;
    const int n = g_counts[e];
    const int row0 = blockIdx.y * 128;
    if (row0 >= n) return;
    const int h0 = blockIdx.x * 128;

    const int tid = threadIdx.x;
    const int wid = tid >> 5, lane = tid & 31;
    const int wm = wid & 1, wn = wid >> 1;        // 2M x 2N
    const int g = lane >> 2, t = lane & 3;

    const __half* ap0 = g_innerh + ((size_t)e * T_TOK + row0 + (tid >> 3)) * FF_DIM + (tid & 7) * 8;
    const __half* bp0 = g_w2h + ((size_t)e * H_DIM + h0 + (tid >> 3)) * FF_DIM + (tid & 7) * 8;
    const uint32_t off0 = (uint32_t)((tid >> 3) * SSH + (tid & 7) * 8) * 2u;
    const uint32_t ostep = 16u * SSH * 2u;
    const size_t pstep = (size_t)16 * FF_DIM;

    auto issue = [&](int s) {
        uint32_t base = sbase + (uint32_t)(s % STAGES) * G2_SZ;
        int k0 = s * 64;
        const __half* ap = ap0 + k0;
        const __half* bp = bp0 + k0;
        uint32_t o = off0;
#pragma unroll
        for (int i = 0; i < 8; i++) {
            CP16(base + o, ap);
            CP16(base + G2_BO + o, bp);
            ap += pstep; bp += pstep; o += ostep;
        }
        CPCOMMIT();
    };

    float acc[4][8][4];
#pragma unroll
    for (int mb = 0; mb < 4; mb++)
#pragma unroll
        for (int nb = 0; nb < 8; nb++)
#pragma unroll
            for (int j = 0; j < 4; j++) acc[mb][nb][j] = 0.f;

    uint32_t aLb0 = (uint32_t)((wm * 64 + (lane & 15)) * SSH) * 2u
                  + (uint32_t)(lane >> 4) * 16u;
    const uint32_t aMstep = 16u * SSH * 2u;
    uint32_t bLb[4];
#pragma unroll
    for (int p = 0; p < 4; p++)
        bLb[p] = (uint32_t)((wn * 64 + p * 16 + ((lane >> 4) << 3) + (lane & 7)) * SSH) * 2u
               + (uint32_t)((lane >> 3) & 1) * 16u;

    issue(0); issue(1);

    const int NIT = FF_DIM / 64;    // 32
    for (int it = 0; it < NIT; ++it) {
        if (it + 1 < NIT) CPWAIT1(); else CPWAIT0();
        __syncthreads();
        if (it + STAGES - 1 < NIT) issue(it + STAGES - 1);

        const uint32_t sb = sbase + (uint32_t)(it % STAGES) * G2_SZ;
        const uint32_t bb = sb + G2_BO;

#pragma unroll
        for (int kk = 0; kk < 4; kk++) {
            const uint32_t ko = (uint32_t)kk * 32u;
            uint32_t a[4][4], b[8][2];
#pragma unroll
            for (int mb = 0; mb < 4; mb++)
                LDSM4(a[mb][0], a[mb][1], a[mb][2], a[mb][3],
                      sb + aLb0 + (uint32_t)mb * aMstep + ko);
#pragma unroll
            for (int p = 0; p < 4; p++)
                LDSM4(b[2*p][0], b[2*p][1], b[2*p+1][0], b[2*p+1][1], bb + bLb[p] + ko);
#pragma unroll
            for (int mb = 0; mb < 4; mb++)
#pragma unroll
                for (int nb = 0; nb < 8; nb++)
                    mma16h(acc[mb][nb], a[mb], b[nb]);
        }
    }

    // non-atomic scatter into per-slot combine buffers
#pragma unroll
    for (int mb = 0; mb < 4; mb++) {
        int r0 = row0 + wm * 64 + mb * 16 + g;
        int r1 = r0 + 8;
        int pk0 = (r0 < n) ? g_tok[e][r0] : -1;
        int pk1 = (r1 < n) ? g_tok[e][r1] : -1;
        float* d0 = (pk0 >= 0)
            ? &g_comb[((size_t)(pk0 >> 16) * T_TOK + (pk0 & 0xFFFF)) * H_DIM] : 0;
        float* d1 = (pk1 >= 0)
            ? &g_comb[((size_t)(pk1 >> 16) * T_TOK + (pk1 & 0xFFFF)) * H_DIM] : 0;
#pragma unroll
        for (int nb = 0; nb < 8; nb++) {
            int col = h0 + wn * 64 + nb * 8 + 2 * t;
            if (d0) { float2 v; v.x = acc[mb][nb][0]; v.y = acc[mb][nb][1];
                      *(float2*)&d0[col] = v; }
            if (d1) { float2 v; v.x = acc[mb][nb][2]; v.y = acc[mb][nb][3];
                      *(float2*)&d1[col] = v; }
        }
    }
}

// ---------------- combine: out = w0*comb0 + w1*comb1; re-zero counts --------
__global__ void combine_kernel(float* __restrict__ out) {
    int idx = blockIdx.x * blockDim.x + threadIdx.x;
    const int nq = T_TOK * H_DIM / 4;
    if (blockIdx.x == 0 && threadIdx.x < NEXP)
        g_counts[threadIdx.x] = 0;           // reset for the NEXT invocation
    if (idx >= nq) return;
    int tk = idx / (H_DIM / 4);
    float w0 = g_wslot[tk], w1 = g_wslot[T_TOK + tk];
    float4 v0 = ((const float4*)g_comb)[idx];
    float4 v1 = ((const float4*)g_comb)[(size_t)(T_TOK * H_DIM / 4) + idx];
    float4 r;
    r.x = w0 * v0.x + w1 * v1.x;
    r.y = w0 * v0.y + w1 * v1.y;
    r.z = w0 * v0.z + w1 * v1.z;
    r.w = w0 * v0.w + w1 * v1.w;
    ((float4*)out)[idx] = r;
}

// ---------------- launch -----------------------------------------------------
extern "C" void kernel_launch(void* const* d_in, const int* in_sizes, int n_in,
                              void* d_out, int out_size) {
    const float* x  = (const float*)d_in[0];  // [2,2048,1024]
    const float* gw = (const float*)d_in[1];  // [8,1024]
    const float* w1 = (const float*)d_in[2];  // [8,2048,1024]
    const float* w2 = (const float*)d_in[3];  // [8,1024,2048]
    const float* w3 = (const float*)d_in[4];  // [8,2048,1024]
    float* out = (float*)d_out;

    const size_t final_elems = (size_t)T_TOK * H_DIM;
    int write_logits = ((size_t)out_size >= final_elems + (size_t)T_TOK * NEXP) ? 1 : 0;
    float* logits = out + final_elems;

    const int dynsm = STAGES * 36864;   // 110592 per CTA -> 2 CTAs/SM
    cudaFuncSetAttribute(gemm1_tc, cudaFuncAttributeMaxDynamicSharedMemorySize, dynsm);
    cudaFuncSetAttribute(gemm2_tc, cudaFuncAttributeMaxDynamicSharedMemorySize, dynsm);

    // prolog: 16384 w1/w3-cvt blocks + 512 router blocks (8 tokens each)
    prolog_kernel<<<WBLK + T_TOK / 8, 256>>>(w1, w3, x, gw, logits, write_logits);

    // gemm1 tiles + appended w2-conversion blocks (flat 1D grid)
    gemm1_tc<<<G1T + W2BLK, 128, dynsm>>>(w2);

    dim3 g2(H_DIM / 128, T_TOK / 128, NEXP);   // (8, 32, 8)
    gemm2_tc<<<g2, 128, dynsm>>>(x);

    combine_kernel<<<(T_TOK * H_DIM / 4 + 255) / 256, 256>>>(out);
}